// round 8
// baseline (speedup 1.0000x reference)
#include <cuda_runtime.h>
#include <cuda_bf16.h>
#include <cstdint>
#include <math.h>

#define NB 8
#define CC 256
#define NPIX 1024
#define HEADS 8
#define HD 128
#define MQKV 3072
#define DIM 1024

// Hamilton tables
__constant__ int   c_IDX[16] = {0,1,2,3, 1,0,3,2, 2,3,0,1, 3,2,1,0};
__constant__ float c_SGN[16] = {1.f,-1.f,-1.f,-1.f, 1.f,1.f,1.f,-1.f,
                                1.f,-1.f,1.f,1.f, 1.f,1.f,-1.f,1.f};

// Scratch (device globals). ALL tensor-core operands pre-tiled + pre-swizzled
// so kernels fetch whole tiles with single cp.async.bulk copies.
// GEMM A tiles: 256 rows x 64B (16KB), tile id = mtile*32 + kt
__device__ __nv_bfloat16 g_WeffH[(size_t)MQKV*DIM];
__device__ __nv_bfloat16 g_WeffL[(size_t)MQKV*DIM];
__device__ __nv_bfloat16 g_WprojH[(size_t)DIM*DIM];
__device__ __nv_bfloat16 g_WprojL[(size_t)DIM*DIM];
// GEMM B tiles: 128 rows x 64B (8KB), tile id = (b*8+ntile)*32 + kt
__device__ __nv_bfloat16 g_XTH[(size_t)NB*NPIX*DIM];
__device__ __nv_bfloat16 g_XTL[(size_t)NB*NPIX*DIM];
__device__ __nv_bfloat16 g_OTH[(size_t)NB*NPIX*DIM];
__device__ __nv_bfloat16 g_OTL[(size_t)NB*NPIX*DIM];
// attention tiles: Q/K 64 rows(n) x 256B(d) (16KB) per (bh, nblock)
__device__ __nv_bfloat16 g_QTH[(size_t)NB*HEADS*NPIX*HD];
__device__ __nv_bfloat16 g_QTL[(size_t)NB*HEADS*NPIX*HD];
__device__ __nv_bfloat16 g_KTH[(size_t)NB*HEADS*NPIX*HD];
__device__ __nv_bfloat16 g_KTL[(size_t)NB*HEADS*NPIX*HD];
// V tiles: 128 rows(d) x 128B(n) (16KB) per (bh, kb)
__device__ __nv_bfloat16 g_VH[(size_t)NB*HEADS*HD*NPIX];
__device__ __nv_bfloat16 g_VL[(size_t)NB*HEADS*HD*NPIX];

// ===========================================================================
// Helpers (base-ISA: cp.async.bulk / mbarrier / ldmatrix / mma.sync)
// ===========================================================================
__device__ __forceinline__ uint32_t smem_u32(const void* p){
  uint32_t a;
  asm("{ .reg .u64 t; cvta.to.shared.u64 t, %1; cvt.u32.u64 %0, t; }"
      : "=r"(a) : "l"(p));
  return a;
}
__device__ __forceinline__ void ldm4(uint32_t r[4], uint32_t addr){
  asm volatile("ldmatrix.sync.aligned.m8n8.x4.shared.b16 {%0,%1,%2,%3}, [%4];"
    : "=r"(r[0]),"=r"(r[1]),"=r"(r[2]),"=r"(r[3]) : "r"(addr));
}
__device__ __forceinline__ void mma16816(float c[4], const uint32_t a[4],
                                         const uint32_t b[2]){
  asm volatile(
    "mma.sync.aligned.m16n8k16.row.col.f32.bf16.bf16.f32 "
    "{%0,%1,%2,%3}, {%4,%5,%6,%7}, {%8,%9}, {%0,%1,%2,%3};"
    : "+f"(c[0]),"+f"(c[1]),"+f"(c[2]),"+f"(c[3])
    : "r"(a[0]),"r"(a[1]),"r"(a[2]),"r"(a[3]), "r"(b[0]),"r"(b[1]));
}
__device__ __forceinline__ uint32_t pkbf2(float a, float b){
  __nv_bfloat162 t = __floats2bfloat162_rn(a, b);
  return *(uint32_t*)&t;
}
#define BULKCP(dst, src, bytes, mb) \
  asm volatile("cp.async.bulk.shared::cluster.global.mbarrier::complete_tx::bytes [%0], [%1], %2, [%3];" \
    :: "r"((uint32_t)(dst)), "l"(src), "r"((uint32_t)(bytes)), "r"((uint32_t)(mb)) : "memory")
#define MBARRIER_INIT(mb, c) \
  asm volatile("mbarrier.init.shared.b64 [%0], %1;" :: "r"((uint32_t)(mb)), "r"((uint32_t)(c)) : "memory")
#define MBARRIER_EXPECT_TX(mb, tx) \
  asm volatile("mbarrier.arrive.expect_tx.shared.b64 _, [%0], %1;" :: "r"((uint32_t)(mb)), "r"((uint32_t)(tx)) : "memory")
#define MBARRIER_WAIT_PARITY(mb, ph) do { \
    uint32_t _m = (uint32_t)(mb); uint32_t _p = (uint32_t)(ph); uint32_t _d; \
    asm volatile("{\n\t.reg .pred p;\n\t" \
        "mbarrier.try_wait.parity.acquire.cta.shared::cta.b64 p, [%1], %2;\n\t" \
        "selp.b32 %0, 1, 0, p;\n\t}" : "=r"(_d) : "r"(_m), "r"(_p) : "memory"); \
    if (!_d) { \
      asm volatile("{\n\t.reg .pred P1;\n\t" \
        "WL_%=:\n\t" \
        "mbarrier.try_wait.parity.acquire.cta.shared::cta.b64 P1, [%0], %1, 0x989680;\n\t" \
        "@P1 bra.uni WD_%=;\n\t" \
        "bra.uni WL_%=;\n\t" \
        "WD_%=:\n\t}" :: "r"(_m), "r"(_p) : "memory"); \
    } \
  } while(0)

// swizzled byte offsets inside tiles (row-major rows of 64/128/256 bytes)
__device__ __forceinline__ uint32_t swz64 (uint32_t r, uint32_t c16){ return r*64u  + ((c16 ^ ((r>>1)&3u))<<4); }
__device__ __forceinline__ uint32_t swz128(uint32_t r, uint32_t c16){ return r*128u + ((c16 ^ (r&7u))<<4); }
__device__ __forceinline__ uint32_t swz256(uint32_t r, uint32_t c16){ return r*256u + ((c16 ^ (r&7u))<<4); }

// ===========================================================================
// Prep: Hamilton-folded weights -> bf16 hi/lo, tiled+swizzled
// ===========================================================================
__global__ void prep_w_kernel(const float* __restrict__ w,
                              __nv_bfloat16* __restrict__ outH,
                              __nv_bfloat16* __restrict__ outL, int is_qkv){
  int idx = blockIdx.x*256 + threadIdx.x;     // chunk id: M*128
  int g = idx >> 7, c = idx & 127;            // c = 16B chunk along k
  int k0 = c*8;
  int qc, o;
  if (is_qkv){ qc = g / 768; o = g - qc*768; } else { qc = g >> 8; o = g & 255; }
  int p = k0 >> 8, cch = k0 & 255;
  float s = c_SGN[qc*4+p];
  const float* src = w + ((size_t)(c_IDX[qc*4+p]*(is_qkv?768:256) + o))*256 + cch;
  float4 v0 = *(const float4*)src;
  float4 v1 = *(const float4*)(src+4);
  float a[8] = {v0.x*s,v0.y*s,v0.z*s,v0.w*s, v1.x*s,v1.y*s,v1.z*s,v1.w*s};
  __nv_bfloat16 h[8]; float hf[8];
  #pragma unroll
  for (int i=0;i<8;i++){ h[i] = __float2bfloat16(a[i]); hf[i] = __bfloat162float(h[i]); }
  uint4 H, L;
  H.x = ((uint32_t)__bfloat16_as_ushort(h[1])<<16)|__bfloat16_as_ushort(h[0]);
  H.y = ((uint32_t)__bfloat16_as_ushort(h[3])<<16)|__bfloat16_as_ushort(h[2]);
  H.z = ((uint32_t)__bfloat16_as_ushort(h[5])<<16)|__bfloat16_as_ushort(h[4]);
  H.w = ((uint32_t)__bfloat16_as_ushort(h[7])<<16)|__bfloat16_as_ushort(h[6]);
  L.x = pkbf2(a[0]-hf[0], a[1]-hf[1]);
  L.y = pkbf2(a[2]-hf[2], a[3]-hf[3]);
  L.z = pkbf2(a[4]-hf[4], a[5]-hf[5]);
  L.w = pkbf2(a[6]-hf[6], a[7]-hf[7]);
  size_t base = ((size_t)((g>>8)*32 + (c>>2)))*16384;
  uint32_t off = swz64(g & 255, c & 3);
  *(uint4*)((char*)outH + base + off) = H;
  *(uint4*)((char*)outL + base + off) = L;
}

// x (b, cch, p, n) fp32 -> XT tiles (b, ntile, kt) bf16 hi/lo
__global__ void prep_xt_kernel(const float* __restrict__ x){
  __shared__ float sm[32][33];
  int b = blockIdx.z, k0 = blockIdx.x*32, n0 = blockIdx.y*32;
  int t = threadIdx.x;
  {
    int kk = t >> 3, n4 = (t & 7) << 2;
    int k = k0 + kk; int p = k >> 8, cch = k & 255;
    float4 v = *(const float4*)&x[((size_t)((b*CC+cch)*4 + p))*NPIX + n0 + n4];
    sm[kk][n4] = v.x; sm[kk][n4+1] = v.y; sm[kk][n4+2] = v.z; sm[kk][n4+3] = v.w;
  }
  __syncthreads();
  {
    int nn = t >> 3, k4 = (t & 7) << 2;
    int n = n0 + nn;
    float a[4];
    #pragma unroll
    for (int i=0;i<4;i++) a[i] = sm[k4+i][nn];
    __nv_bfloat16 hh[4];
    #pragma unroll
    for (int i=0;i<4;i++) hh[i] = __float2bfloat16(a[i]);
    uint2 hp = make_uint2(pkbf2(__bfloat162float(hh[0]), __bfloat162float(hh[1])),
                          pkbf2(__bfloat162float(hh[2]), __bfloat162float(hh[3])));
    uint2 lp = make_uint2(pkbf2(a[0]-__bfloat162float(hh[0]), a[1]-__bfloat162float(hh[1])),
                          pkbf2(a[2]-__bfloat162float(hh[2]), a[3]-__bfloat162float(hh[3])));
    size_t tb = ((size_t)((b*8 + (n>>7))*32 + (k0>>5)))*8192;
    uint32_t off = swz64(n & 127, k4 >> 3) + ((k4 >> 2) & 1)*8;
    *(uint2*)((char*)g_XTH + tb + off) = hp;
    *(uint2*)((char*)g_XTL + tb + off) = lp;
  }
}

// ===========================================================================
// mma.sync GEMM: 256m x 128n per CTA, K=1024, bf16x3, BK=32 bulk-fed.
// 256 threads, 8 warps (4m x 2n), warp tile 64x64. Grouped mma passes
// (same-accumulator reuse distance = 32) — the empirically fastest schedule.
// MODE 0: A=Weff (M=3072), B=XT; each CTA's m-tile is pure Q, K or V.
// MODE 1: A=Wproj, B=OT -> final output (+bias)
// ===========================================================================
#define GSTG 49152u
#define GEMM_SMEM 136192u   // max(1024 + 2*GSTG, 1024 + 256*132*4 epilogue T)

template<int MODE>
__global__ __launch_bounds__(256, 1) void gemm_mma(const float* __restrict__ bias,
                                                   float* __restrict__ outp){
  extern __shared__ char smem[];
  const uint32_t sb = smem_u32(smem);
  const int tid = threadIdx.x;
  const int wid = tid >> 5, lane = tid & 31;
  const int mt = blockIdx.x;
  const int b  = blockIdx.y >> 3;
  const int nt = blockIdx.y & 7;
  const int m0 = mt*256, n0 = nt*128;
  const int wm = (wid >> 1) * 64;
  const int wn = (wid & 1) * 64;

  const char* Ahb = (const char*)(MODE==0 ? g_WeffH : g_WprojH) + (size_t)mt*32*16384;
  const char* Alb = (const char*)(MODE==0 ? g_WeffL : g_WprojL) + (size_t)mt*32*16384;
  const char* Bhb = (const char*)(MODE==0 ? g_XTH : g_OTH) + (size_t)((b*8+nt)*32)*8192;
  const char* Blb = (const char*)(MODE==0 ? g_XTL : g_OTL) + (size_t)((b*8+nt)*32)*8192;

  if (tid == 0){ MBARRIER_INIT(sb+8, 1); MBARRIER_INIT(sb+16, 1); }
  __syncthreads();

  float acc[4][8][4];
  #pragma unroll
  for (int i=0;i<4;i++)
    #pragma unroll
    for (int j=0;j<8;j++)
      #pragma unroll
      for (int r=0;r<4;r++) acc[i][j][r] = 0.f;

  auto issue = [&](int kt){
    if (tid == 0){
      int buf = kt & 1;
      uint32_t mb = sb + 8 + buf*8;
      MBARRIER_EXPECT_TX(mb, GSTG);
      uint32_t d = sb + 1024 + buf*GSTG;
      BULKCP(d,         Ahb + (size_t)kt*16384, 16384, mb);
      BULKCP(d+16384,   Alb + (size_t)kt*16384, 16384, mb);
      BULKCP(d+32768,   Bhb + (size_t)kt*8192,  8192,  mb);
      BULKCP(d+40960,   Blb + (size_t)kt*8192,  8192,  mb);
    }
  };

  issue(0);
  for (int kt = 0; kt < 32; kt++){
    if (kt + 1 < 32) issue(kt+1);
    MBARRIER_WAIT_PARITY(sb + 8 + (kt&1)*8, (kt>>1)&1);
    const uint32_t st = sb + 1024 + (kt&1)*GSTG;

    #pragma unroll
    for (int ks = 0; ks < 2; ks++){
      uint32_t ah[4][4], al[4][4], bh[8][2], bl[8][2];
      #pragma unroll
      for (int mi = 0; mi < 4; mi++){
        uint32_t row = wm + mi*16 + (lane & 15);
        uint32_t c16 = ks*2 + (lane >> 4);
        uint32_t addr = st + swz64(row, c16);
        ldm4(ah[mi], addr);
        ldm4(al[mi], addr + 16384);
      }
      #pragma unroll
      for (int np = 0; np < 4; np++){
        uint32_t row = wn + np*16 + (lane >> 4)*8 + (lane & 7);
        uint32_t c16 = ks*2 + ((lane >> 3) & 1);
        uint32_t addr = st + 32768 + swz64(row, c16);
        uint32_t r[4];
        ldm4(r, addr);
        bh[np*2][0]=r[0]; bh[np*2][1]=r[1]; bh[np*2+1][0]=r[2]; bh[np*2+1][1]=r[3];
        ldm4(r, addr + 8192);
        bl[np*2][0]=r[0]; bl[np*2][1]=r[1]; bl[np*2+1][0]=r[2]; bl[np*2+1][1]=r[3];
      }
      #pragma unroll
      for (int mi=0;mi<4;mi++)
        #pragma unroll
        for (int ni=0;ni<8;ni++) mma16816(acc[mi][ni], ah[mi], bh[ni]);
      #pragma unroll
      for (int mi=0;mi<4;mi++)
        #pragma unroll
        for (int ni=0;ni<8;ni++) mma16816(acc[mi][ni], ah[mi], bl[ni]);
      #pragma unroll
      for (int mi=0;mi<4;mi++)
        #pragma unroll
        for (int ni=0;ni<8;ni++) mma16816(acc[mi][ni], al[mi], bh[ni]);
    }
    __syncthreads();
  }

  if (MODE == 1){
    // final output: out[(b, cch, qc, n)] = acc + bias
    #pragma unroll
    for (int mi=0;mi<4;mi++)
      #pragma unroll
      for (int half=0; half<2; half++){
        int gm = m0 + wm + mi*16 + (lane >> 2) + half*8;
        float bi = bias[gm];
        int qc = gm >> 8; int cch = gm & 255;
        float* dst = outp + ((size_t)((b*CC + cch)*4 + qc))*NPIX;
        #pragma unroll
        for (int ni=0;ni<8;ni++){
          int nn = n0 + wn + ni*8 + (lane & 3)*2;
          float2 v = make_float2(acc[mi][ni][half*2+0] + bi,
                                 acc[mi][ni][half*2+1] + bi);
          *(float2*)&dst[nn] = v;
        }
      }
    return;
  }

  // ---- MODE 0 epilogue: region = Q(0) / K(1) / V(2) ----
  const int region = mt % 3;
  const int qc = mt / 3;
  if (region == 2){
    // V: direct hi/lo stores into (d, n) tiles
    #pragma unroll
    for (int mi=0;mi<4;mi++)
      #pragma unroll
      for (int half=0; half<2; half++){
        int gm = m0 + wm + mi*16 + (lane >> 2) + half*8;
        float bi = bias[gm];
        int o = gm - qc*768; int cch = o & 255;
        int ch = (qc << 8) | cch; int hh = ch >> 7; int dd = ch & 127;
        size_t bhbase = ((size_t)(b*HEADS + hh))*16*16384;
        #pragma unroll
        for (int ni=0;ni<8;ni++){
          int nn = n0 + wn + ni*8 + (lane & 3)*2;
          float v0 = acc[mi][ni][half*2+0] + bi;
          float v1 = acc[mi][ni][half*2+1] + bi;
          __nv_bfloat16 h0 = __float2bfloat16(v0), h1 = __float2bfloat16(v1);
          size_t tb = bhbase + (size_t)(nn>>6)*16384;
          uint32_t off = swz128(dd, (nn&63)>>3) + (nn&7)*2;
          *(uint32_t*)((char*)g_VH + tb + off) =
              pkbf2(__bfloat162float(h0), __bfloat162float(h1));
          *(uint32_t*)((char*)g_VL + tb + off) =
              pkbf2(v0-__bfloat162float(h0), v1-__bfloat162float(h1));
        }
      }
  } else {
    // Q/K: stage fp32 into smem (scale folded), transpose, emit (n,d) tiles
    float* T = (float*)(smem + 1024);   // 256 x 132 fp32 = 135168 B
    const float scl = (region == 0) ? 0.12751875542484462f  // qscale*log2e
                                    : 1.f;
    #pragma unroll
    for (int mi=0;mi<4;mi++)
      #pragma unroll
      for (int half=0; half<2; half++){
        int gm = m0 + wm + mi*16 + (lane >> 2) + half*8;
        int row = gm - m0;
        float bi = bias[gm];
        #pragma unroll
        for (int ni=0;ni<8;ni++){
          int nn = wn + ni*8 + (lane & 3)*2;
          T[row*132 + nn]     = (acc[mi][ni][half*2+0] + bi)*scl;
          T[row*132 + nn + 1] = (acc[mi][ni][half*2+1] + bi)*scl;
        }
      }
    __syncthreads();

    char* dh = (region == 0) ? (char*)g_QTH : (char*)g_KTH;
    char* dl = (region == 0) ? (char*)g_QTL : (char*)g_KTL;
    const int nl = tid & 127;
    const int hp = tid >> 7;            // head parity within tile
    const int n = n0 + nl;
    const int head = qc*2 + hp;
    const size_t tb = ((size_t)((b*HEADS + head)*16 + (n>>6)))*16384;
    const uint32_t r6 = n & 63;
    #pragma unroll
    for (int c16 = 0; c16 < 16; c16++){
      float a[8]; __nv_bfloat16 h[8]; float hf[8];
      #pragma unroll
      for (int i=0;i<8;i++) a[i] = T[(hp*128 + c16*8 + i)*132 + nl];
      #pragma unroll
      for (int i=0;i<8;i++){ h[i] = __float2bfloat16(a[i]); hf[i] = __bfloat162float(h[i]); }
      uint4 H, L;
      H.x = pkbf2(hf[0],hf[1]); H.y = pkbf2(hf[2],hf[3]);
      H.z = pkbf2(hf[4],hf[5]); H.w = pkbf2(hf[6],hf[7]);
      L.x = pkbf2(a[0]-hf[0], a[1]-hf[1]);
      L.y = pkbf2(a[2]-hf[2], a[3]-hf[3]);
      L.z = pkbf2(a[4]-hf[4], a[5]-hf[5]);
      L.w = pkbf2(a[6]-hf[6], a[7]-hf[7]);
      uint32_t off = swz256(r6, c16);
      *(uint4*)(dh + tb + off) = H;
      *(uint4*)(dl + tb + off) = L;
    }
  }
}

// ===========================================================================
// Flash attention, mma.sync bf16x3, bulk-copy fed, GROUPED mma passes.
// CTA = (b,h) x 128 queries, 256 thr, 8 warps x 16 q-rows.
// ===========================================================================
#define ASTG 65536u
#define AT_SMEM (1024u + 2u*ASTG)

__global__ __launch_bounds__(256, 1) void attn_mma(){
  extern __shared__ char smem[];
  const uint32_t sb = smem_u32(smem);
  const int tid = threadIdx.x;
  const int wid = tid >> 5, lane = tid & 31;
  const int bh = blockIdx.y;
  const int qi = blockIdx.x;           // q block of 128
  const int q0 = qi * 128;
  const int b = bh >> 3, h = bh & 7;

  if (tid == 0){
    MBARRIER_INIT(sb+8, 1); MBARRIER_INIT(sb+16, 1); MBARRIER_INIT(sb+24, 1);
  }
  __syncthreads();

  // ---- Q load: 2 tiles hi + 2 tiles lo = 64KB into stage0 region
  if (tid == 0){
    MBARRIER_EXPECT_TX(sb+24, 65536);
    const char* qh_g = (const char*)g_QTH + ((size_t)bh*16 + qi*2)*16384;
    const char* ql_g = (const char*)g_QTL + ((size_t)bh*16 + qi*2)*16384;
    BULKCP(sb+1024,         qh_g, 32768, sb+24);
    BULKCP(sb+1024+32768,   ql_g, 32768, sb+24);
  }
  MBARRIER_WAIT_PARITY(sb+24, 0);

  uint32_t qfh[8][4], qfl[8][4];
  {
    uint32_t row = wid*16 + (lane & 15);
    uint32_t base = sb + 1024 + (row >> 6)*16384;
    uint32_t r6 = row & 63;
    #pragma unroll
    for (int kf = 0; kf < 8; kf++){
      uint32_t c16 = kf*2 + (lane >> 4);
      uint32_t addr = base + swz256(r6, c16);
      ldm4(qfh[kf], addr);
      ldm4(qfl[kf], addr + 32768);
    }
  }
  __syncthreads();   // Q consumed; stage0 reusable

  const char* kh_g = (const char*)g_KTH + (size_t)bh*16*16384;
  const char* kl_g = (const char*)g_KTL + (size_t)bh*16*16384;
  const char* vh_g = (const char*)g_VH  + (size_t)bh*16*16384;
  const char* vl_g = (const char*)g_VL  + (size_t)bh*16*16384;

  auto issueKV = [&](int kb){
    if (tid == 0){
      int buf = kb & 1;
      uint32_t mb = sb + 8 + buf*8;
      MBARRIER_EXPECT_TX(mb, ASTG);
      uint32_t d = sb + 1024 + buf*ASTG;
      BULKCP(d,         kh_g + (size_t)kb*16384, 16384, mb);
      BULKCP(d+16384,   kl_g + (size_t)kb*16384, 16384, mb);
      BULKCP(d+32768,   vh_g + (size_t)kb*16384, 16384, mb);
      BULKCP(d+49152,   vl_g + (size_t)kb*16384, 16384, mb);
    }
  };

  float accO[16][4];
  #pragma unroll
  for (int i=0;i<16;i++)
    #pragma unroll
    for (int r=0;r<4;r++) accO[i][r] = 0.f;
  float m0r = -1e30f, m1r = -1e30f, l0 = 0.f, l1 = 0.f;

  issueKV(0);
  for (int kb = 0; kb < 16; kb++){
    if (kb + 1 < 16) issueKV(kb+1);
    MBARRIER_WAIT_PARITY(sb + 8 + (kb&1)*8, (kb>>1)&1);
    const uint32_t st = sb + 1024 + (kb&1)*ASTG;

    // ---- S = Q K^T  (16q x 64k per warp), bf16x3, grouped passes
    float S[8][4];
    #pragma unroll
    for (int i=0;i<8;i++)
      #pragma unroll
      for (int r=0;r<4;r++) S[i][r] = 0.f;
    #pragma unroll
    for (int kf = 0; kf < 8; kf++){
      uint32_t bh2[8][2], bl2[8][2];
      #pragma unroll
      for (int np = 0; np < 4; np++){
        uint32_t row = np*16 + (lane >> 4)*8 + (lane & 7);
        uint32_t c16 = kf*2 + ((lane >> 3) & 1);
        uint32_t addr = st + swz256(row, c16);
        uint32_t r[4];
        ldm4(r, addr);
        bh2[np*2][0]=r[0]; bh2[np*2][1]=r[1]; bh2[np*2+1][0]=r[2]; bh2[np*2+1][1]=r[3];
        ldm4(r, addr + 16384);
        bl2[np*2][0]=r[0]; bl2[np*2][1]=r[1]; bl2[np*2+1][0]=r[2]; bl2[np*2+1][1]=r[3];
      }
      #pragma unroll
      for (int ni=0; ni<8; ni++) mma16816(S[ni], qfh[kf], bh2[ni]);
      #pragma unroll
      for (int ni=0; ni<8; ni++) mma16816(S[ni], qfl[kf], bh2[ni]);
      #pragma unroll
      for (int ni=0; ni<8; ni++) mma16816(S[ni], qfh[kf], bl2[ni]);
    }

    // ---- online softmax (log2 domain; log2e folded into Q)
    float mx0 = -1e30f, mx1 = -1e30f;
    #pragma unroll
    for (int i=0;i<8;i++){
      mx0 = fmaxf(mx0, fmaxf(S[i][0], S[i][1]));
      mx1 = fmaxf(mx1, fmaxf(S[i][2], S[i][3]));
    }
    mx0 = fmaxf(mx0, __shfl_xor_sync(0xffffffffu, mx0, 1));
    mx0 = fmaxf(mx0, __shfl_xor_sync(0xffffffffu, mx0, 2));
    mx1 = fmaxf(mx1, __shfl_xor_sync(0xffffffffu, mx1, 1));
    mx1 = fmaxf(mx1, __shfl_xor_sync(0xffffffffu, mx1, 2));
    float mn0 = fmaxf(m0r, mx0), mn1 = fmaxf(m1r, mx1);
    float al0 = exp2f(m0r - mn0), al1 = exp2f(m1r - mn1);
    m0r = mn0; m1r = mn1;

    float rs0 = 0.f, rs1 = 0.f;
    uint32_t ph[4][4], pl[4][4];
    #pragma unroll
    for (int nf = 0; nf < 8; nf++){
      float p0 = exp2f(S[nf][0] - mn0);
      float p1 = exp2f(S[nf][1] - mn0);
      float p2 = exp2f(S[nf][2] - mn1);
      float p3 = exp2f(S[nf][3] - mn1);
      rs0 += p0 + p1; rs1 += p2 + p3;
      __nv_bfloat16 h0 = __float2bfloat16(p0), h1 = __float2bfloat16(p1);
      __nv_bfloat16 h2 = __float2bfloat16(p2), h3 = __float2bfloat16(p3);
      int kf = nf >> 1, pc = (nf & 1)*2;
      ph[kf][pc+0] = pkbf2(__bfloat162float(h0), __bfloat162float(h1));
      ph[kf][pc+1] = pkbf2(__bfloat162float(h2), __bfloat162float(h3));
      pl[kf][pc+0] = pkbf2(p0-__bfloat162float(h0), p1-__bfloat162float(h1));
      pl[kf][pc+1] = pkbf2(p2-__bfloat162float(h2), p3-__bfloat162float(h3));
    }
    rs0 += __shfl_xor_sync(0xffffffffu, rs0, 1);
    rs0 += __shfl_xor_sync(0xffffffffu, rs0, 2);
    rs1 += __shfl_xor_sync(0xffffffffu, rs1, 1);
    rs1 += __shfl_xor_sync(0xffffffffu, rs1, 2);
    l0 = l0*al0 + rs0; l1 = l1*al1 + rs1;

    #pragma unroll
    for (int i=0;i<16;i++){
      accO[i][0] *= al0; accO[i][1] *= al0;
      accO[i][2] *= al1; accO[i][3] *= al1;
    }

    // ---- accO += P V  (16q x 128d per warp), bf16x3, grouped passes
    const uint32_t vb = st + 32768;
    #pragma unroll
    for (int kf = 0; kf < 4; kf++){
      #pragma unroll
      for (int hh2 = 0; hh2 < 2; hh2++){           // np-halves of 4
        uint32_t vh2[8][2], vl2[8][2];
        #pragma unroll
        for (int j = 0; j < 4; j++){
          int np = hh2*4 + j;
          uint32_t row = np*16 + (lane >> 4)*8 + (lane & 7);
          uint32_t c16 = kf*2 + ((lane >> 3) & 1);
          uint32_t addr = vb + swz128(row, c16);
          uint32_t r[4];
          ldm4(r, addr);
          vh2[j*2][0]=r[0]; vh2[j*2][1]=r[1]; vh2[j*2+1][0]=r[2]; vh2[j*2+1][1]=r[3];
          ldm4(r, addr + 16384);
          vl2[j*2][0]=r[0]; vl2[j*2][1]=r[1]; vl2[j*2+1][0]=r[2]; vl2[j*2+1][1]=r[3];
        }
        #pragma unroll
        for (int j=0; j<8; j++) mma16816(accO[hh2*8+j], ph[kf], vh2[j]);
        #pragma unroll
        for (int j=0; j<8; j++) mma16816(accO[hh2*8+j], pl[kf], vh2[j]);
        #pragma unroll
        for (int j=0; j<8; j++) mma16816(accO[hh2*8+j], ph[kf], vl2[j]);
      }
    }
    __syncthreads();
  }

  // ---- epilogue: O/l -> bf16 hi/lo into tiled OT
  float inv0 = 1.f / l0, inv1 = 1.f / l1;
  int na = q0 + wid*16 + (lane >> 2);
  int nb2 = na + 8;
  #pragma unroll
  for (int nf = 0; nf < 16; nf++){
    int ch = h*HD + nf*8 + (lane & 3)*2;
    float v0 = accO[nf][0]*inv0, v1 = accO[nf][1]*inv0;
    float v2 = accO[nf][2]*inv1, v3 = accO[nf][3]*inv1;
    __nv_bfloat16 h0 = __float2bfloat16(v0), h1 = __float2bfloat16(v1);
    __nv_bfloat16 h2 = __float2bfloat16(v2), h3 = __float2bfloat16(v3);
    size_t tba = ((size_t)((b*8 + (na>>7))*32 + (ch>>5)))*8192;
    size_t tbb = ((size_t)((b*8 + (nb2>>7))*32 + (ch>>5)))*8192;
    uint32_t ofa = swz64(na & 127, (ch>>3)&3) + (ch&7)*2;
    uint32_t ofb = swz64(nb2 & 127, (ch>>3)&3) + (ch&7)*2;
    *(uint32_t*)((char*)g_OTH + tba + ofa) = pkbf2(__bfloat162float(h0), __bfloat162float(h1));
    *(uint32_t*)((char*)g_OTL + tba + ofa) = pkbf2(v0-__bfloat162float(h0), v1-__bfloat162float(h1));
    *(uint32_t*)((char*)g_OTH + tbb + ofb) = pkbf2(__bfloat162float(h2), __bfloat162float(h3));
    *(uint32_t*)((char*)g_OTL + tbb + ofb) = pkbf2(v2-__bfloat162float(h2), v3-__bfloat162float(h3));
  }
}

// ---------------------------------------------------------------------------
// Quaternion depthwise 3x3, accumulates into final output.
// ---------------------------------------------------------------------------
__global__ __launch_bounds__(256) void qdwconv_kernel(const float* __restrict__ x,
                                                      const float* __restrict__ w_pe,
                                                      const float* __restrict__ b_pe,
                                                      float* __restrict__ outp){
  __shared__ float xs[4][1024];
  __shared__ float wt[4][4][9];
  const int bid = blockIdx.x;
  const int c = bid & 255, b = bid >> 8;
  const int tid = threadIdx.x;

  #pragma unroll
  for (int p=0;p<4;p++){
    const float* xp = x + ((size_t)((b*CC + c)*4 + p))*NPIX;
    for (int k=tid; k<1024; k+=256) xs[p][k] = xp[k];
  }
  if (tid < 144){
    int qc = tid/36, p = (tid/9)&3, t = tid%9;
    wt[qc][p][t] = c_SGN[qc*4+p] * w_pe[(c_IDX[qc*4+p]*CC + c)*9 + t];
  }
  __syncthreads();

  float bia[4];
  #pragma unroll
  for (int qc=0;qc<4;qc++) bia[qc] = b_pe[qc*CC + c];

  for (int k=tid; k<1024; k+=256){
    int hh = k >> 5, ww = k & 31;
    float acc[4] = {bia[0],bia[1],bia[2],bia[3]};
    #pragma unroll
    for (int p=0;p<4;p++){
      #pragma unroll
      for (int kh=0;kh<3;kh++){
        int h2 = hh + kh - 1;
        if (h2 < 0 || h2 > 31) continue;
        #pragma unroll
        for (int kw=0;kw<3;kw++){
          int w2 = ww + kw - 1;
          if (w2 < 0 || w2 > 31) continue;
          float xv = xs[p][h2*32 + w2];
          #pragma unroll
          for (int qc=0;qc<4;qc++) acc[qc] = fmaf(wt[qc][p][kh*3+kw], xv, acc[qc]);
        }
      }
    }
    #pragma unroll
    for (int qc=0;qc<4;qc++)
      outp[((size_t)((b*CC + c)*4 + qc))*NPIX + k] += acc[qc];
  }
}

// ---------------------------------------------------------------------------
extern "C" void kernel_launch(void* const* d_in, const int* in_sizes, int n_in,
                              void* d_out, int out_size){
  const float* x      = (const float*)d_in[0];
  const float* w_qkv  = (const float*)d_in[1];
  const float* b_qkv  = (const float*)d_in[2];
  const float* w_proj = (const float*)d_in[3];
  const float* b_proj = (const float*)d_in[4];
  const float* w_pe   = (const float*)d_in[5];
  const float* b_pe   = (const float*)d_in[6];
  float* outp = (float*)d_out;

  (void)in_sizes; (void)n_in; (void)out_size;

  cudaFuncSetAttribute(gemm_mma<0>, cudaFuncAttributeMaxDynamicSharedMemorySize,
                       GEMM_SMEM);
  cudaFuncSetAttribute(gemm_mma<1>, cudaFuncAttributeMaxDynamicSharedMemorySize,
                       GEMM_SMEM);
  cudaFuncSetAttribute(attn_mma, cudaFuncAttributeMaxDynamicSharedMemorySize,
                       AT_SMEM);

  // Weight prep (tiled + swizzled, bf16 hi/lo)
  __nv_bfloat16 *weffH, *weffL, *wprojH, *wprojL;
  cudaGetSymbolAddress((void**)&weffH, g_WeffH);
  cudaGetSymbolAddress((void**)&weffL, g_WeffL);
  cudaGetSymbolAddress((void**)&wprojH, g_WprojH);
  cudaGetSymbolAddress((void**)&wprojL, g_WprojL);
  prep_w_kernel<<< MQKV*128/256, 256 >>>(w_qkv, weffH, weffL, 1);
  prep_w_kernel<<< DIM*128/256, 256 >>>(w_proj, wprojH, wprojL, 0);
  prep_xt_kernel<<< dim3(32,32,8), 256 >>>(x);

  // QKV GEMM: emits Q/K (n,d) and V (d,n) bf16 hi/lo tiles directly
  gemm_mma<0><<< dim3(12,64), 256, GEMM_SMEM >>>(b_qkv, nullptr);

  // Attention: mma.sync flash, 8 q-tiles x 64 (b,h)
  attn_mma<<< dim3(8,64), 256, AT_SMEM >>>();

  // Proj: (1024 x 8192) mma.sync bf16x3 -> final output (+bias)
  gemm_mma<1><<< dim3(4,64), 256, GEMM_SMEM >>>(b_proj, outp);

  // Positional depthwise conv, accumulate
  qdwconv_kernel<<< NB*CC, 256 >>>(x, w_pe, b_pe, outp);
}

// round 9
// speedup vs baseline: 1.0350x; 1.0350x over previous
#include <cuda_runtime.h>
#include <cuda_bf16.h>
#include <cstdint>
#include <math.h>

#define NB 8
#define CC 256
#define NPIX 1024
#define HEADS 8
#define HD 128
#define MQKV 3072
#define DIM 1024

// Hamilton tables
__constant__ int   c_IDX[16] = {0,1,2,3, 1,0,3,2, 2,3,0,1, 3,2,1,0};
__constant__ float c_SGN[16] = {1.f,-1.f,-1.f,-1.f, 1.f,1.f,1.f,-1.f,
                                1.f,-1.f,1.f,1.f, 1.f,1.f,-1.f,1.f};

// Scratch (device globals). ALL tensor-core operands pre-tiled + pre-swizzled
// so kernels fetch whole tiles with single cp.async.bulk copies.
__device__ __nv_bfloat16 g_WeffH[(size_t)MQKV*DIM];
__device__ __nv_bfloat16 g_WeffL[(size_t)MQKV*DIM];
__device__ __nv_bfloat16 g_WprojH[(size_t)DIM*DIM];
__device__ __nv_bfloat16 g_WprojL[(size_t)DIM*DIM];
__device__ __nv_bfloat16 g_XTH[(size_t)NB*NPIX*DIM];
__device__ __nv_bfloat16 g_XTL[(size_t)NB*NPIX*DIM];
__device__ __nv_bfloat16 g_OTH[(size_t)NB*NPIX*DIM];
__device__ __nv_bfloat16 g_OTL[(size_t)NB*NPIX*DIM];
__device__ __nv_bfloat16 g_QTH[(size_t)NB*HEADS*NPIX*HD];
__device__ __nv_bfloat16 g_QTL[(size_t)NB*HEADS*NPIX*HD];
__device__ __nv_bfloat16 g_KTH[(size_t)NB*HEADS*NPIX*HD];
__device__ __nv_bfloat16 g_KTL[(size_t)NB*HEADS*NPIX*HD];
__device__ __nv_bfloat16 g_VH[(size_t)NB*HEADS*HD*NPIX];
__device__ __nv_bfloat16 g_VL[(size_t)NB*HEADS*HD*NPIX];

// ===========================================================================
// Helpers (base-ISA: cp.async.bulk / mbarrier / ldmatrix / mma.sync)
// ===========================================================================
__device__ __forceinline__ uint32_t smem_u32(const void* p){
  uint32_t a;
  asm("{ .reg .u64 t; cvta.to.shared.u64 t, %1; cvt.u32.u64 %0, t; }"
      : "=r"(a) : "l"(p));
  return a;
}
__device__ __forceinline__ void ldm4(uint32_t r[4], uint32_t addr){
  asm volatile("ldmatrix.sync.aligned.m8n8.x4.shared.b16 {%0,%1,%2,%3}, [%4];"
    : "=r"(r[0]),"=r"(r[1]),"=r"(r[2]),"=r"(r[3]) : "r"(addr));
}
__device__ __forceinline__ void mma16816(float c[4], const uint32_t a[4],
                                         const uint32_t b[2]){
  asm volatile(
    "mma.sync.aligned.m16n8k16.row.col.f32.bf16.bf16.f32 "
    "{%0,%1,%2,%3}, {%4,%5,%6,%7}, {%8,%9}, {%0,%1,%2,%3};"
    : "+f"(c[0]),"+f"(c[1]),"+f"(c[2]),"+f"(c[3])
    : "r"(a[0]),"r"(a[1]),"r"(a[2]),"r"(a[3]), "r"(b[0]),"r"(b[1]));
}
__device__ __forceinline__ uint32_t pkbf2(float a, float b){
  __nv_bfloat162 t = __floats2bfloat162_rn(a, b);
  return *(uint32_t*)&t;
}
#define BULKCP(dst, src, bytes, mb) \
  asm volatile("cp.async.bulk.shared::cluster.global.mbarrier::complete_tx::bytes [%0], [%1], %2, [%3];" \
    :: "r"((uint32_t)(dst)), "l"(src), "r"((uint32_t)(bytes)), "r"((uint32_t)(mb)) : "memory")
#define MBARRIER_INIT(mb, c) \
  asm volatile("mbarrier.init.shared.b64 [%0], %1;" :: "r"((uint32_t)(mb)), "r"((uint32_t)(c)) : "memory")
#define MBARRIER_EXPECT_TX(mb, tx) \
  asm volatile("mbarrier.arrive.expect_tx.shared.b64 _, [%0], %1;" :: "r"((uint32_t)(mb)), "r"((uint32_t)(tx)) : "memory")
#define MBARRIER_WAIT_PARITY(mb, ph) do { \
    uint32_t _m = (uint32_t)(mb); uint32_t _p = (uint32_t)(ph); uint32_t _d; \
    asm volatile("{\n\t.reg .pred p;\n\t" \
        "mbarrier.try_wait.parity.acquire.cta.shared::cta.b64 p, [%1], %2;\n\t" \
        "selp.b32 %0, 1, 0, p;\n\t}" : "=r"(_d) : "r"(_m), "r"(_p) : "memory"); \
    if (!_d) { \
      asm volatile("{\n\t.reg .pred P1;\n\t" \
        "WL_%=:\n\t" \
        "mbarrier.try_wait.parity.acquire.cta.shared::cta.b64 P1, [%0], %1, 0x989680;\n\t" \
        "@P1 bra.uni WD_%=;\n\t" \
        "bra.uni WL_%=;\n\t" \
        "WD_%=:\n\t}" :: "r"(_m), "r"(_p) : "memory"); \
    } \
  } while(0)

// swizzled byte offsets inside tiles (row-major rows of 64/128/256 bytes)
__device__ __forceinline__ uint32_t swz64 (uint32_t r, uint32_t c16){ return r*64u  + ((c16 ^ ((r>>1)&3u))<<4); }
__device__ __forceinline__ uint32_t swz128(uint32_t r, uint32_t c16){ return r*128u + ((c16 ^ (r&7u))<<4); }
__device__ __forceinline__ uint32_t swz256(uint32_t r, uint32_t c16){ return r*256u + ((c16 ^ (r&7u))<<4); }

// ===========================================================================
// Prep: Hamilton-folded weights -> bf16 hi/lo, tiled+swizzled
// ===========================================================================
__global__ void prep_w_kernel(const float* __restrict__ w,
                              __nv_bfloat16* __restrict__ outH,
                              __nv_bfloat16* __restrict__ outL, int is_qkv){
  int idx = blockIdx.x*256 + threadIdx.x;     // chunk id: M*128
  int g = idx >> 7, c = idx & 127;            // c = 16B chunk along k
  int k0 = c*8;
  int qc, o;
  if (is_qkv){ qc = g / 768; o = g - qc*768; } else { qc = g >> 8; o = g & 255; }
  int p = k0 >> 8, cch = k0 & 255;
  float s = c_SGN[qc*4+p];
  const float* src = w + ((size_t)(c_IDX[qc*4+p]*(is_qkv?768:256) + o))*256 + cch;
  float4 v0 = *(const float4*)src;
  float4 v1 = *(const float4*)(src+4);
  float a[8] = {v0.x*s,v0.y*s,v0.z*s,v0.w*s, v1.x*s,v1.y*s,v1.z*s,v1.w*s};
  __nv_bfloat16 h[8]; float hf[8];
  #pragma unroll
  for (int i=0;i<8;i++){ h[i] = __float2bfloat16(a[i]); hf[i] = __bfloat162float(h[i]); }
  uint4 H, L;
  H.x = ((uint32_t)__bfloat16_as_ushort(h[1])<<16)|__bfloat16_as_ushort(h[0]);
  H.y = ((uint32_t)__bfloat16_as_ushort(h[3])<<16)|__bfloat16_as_ushort(h[2]);
  H.z = ((uint32_t)__bfloat16_as_ushort(h[5])<<16)|__bfloat16_as_ushort(h[4]);
  H.w = ((uint32_t)__bfloat16_as_ushort(h[7])<<16)|__bfloat16_as_ushort(h[6]);
  L.x = pkbf2(a[0]-hf[0], a[1]-hf[1]);
  L.y = pkbf2(a[2]-hf[2], a[3]-hf[3]);
  L.z = pkbf2(a[4]-hf[4], a[5]-hf[5]);
  L.w = pkbf2(a[6]-hf[6], a[7]-hf[7]);
  size_t base = ((size_t)((g>>8)*32 + (c>>2)))*16384;
  uint32_t off = swz64(g & 255, c & 3);
  *(uint4*)((char*)outH + base + off) = H;
  *(uint4*)((char*)outL + base + off) = L;
}

// x (b, cch, p, n) fp32 -> XT tiles (b, ntile, kt) bf16 hi/lo
__global__ void prep_xt_kernel(const float* __restrict__ x){
  __shared__ float sm[32][33];
  int b = blockIdx.z, k0 = blockIdx.x*32, n0 = blockIdx.y*32;
  int t = threadIdx.x;
  {
    int kk = t >> 3, n4 = (t & 7) << 2;
    int k = k0 + kk; int p = k >> 8, cch = k & 255;
    float4 v = *(const float4*)&x[((size_t)((b*CC+cch)*4 + p))*NPIX + n0 + n4];
    sm[kk][n4] = v.x; sm[kk][n4+1] = v.y; sm[kk][n4+2] = v.z; sm[kk][n4+3] = v.w;
  }
  __syncthreads();
  {
    int nn = t >> 3, k4 = (t & 7) << 2;
    int n = n0 + nn;
    float a[4];
    #pragma unroll
    for (int i=0;i<4;i++) a[i] = sm[k4+i][nn];
    __nv_bfloat16 hh[4];
    #pragma unroll
    for (int i=0;i<4;i++) hh[i] = __float2bfloat16(a[i]);
    uint2 hp = make_uint2(pkbf2(__bfloat162float(hh[0]), __bfloat162float(hh[1])),
                          pkbf2(__bfloat162float(hh[2]), __bfloat162float(hh[3])));
    uint2 lp = make_uint2(pkbf2(a[0]-__bfloat162float(hh[0]), a[1]-__bfloat162float(hh[1])),
                          pkbf2(a[2]-__bfloat162float(hh[2]), a[3]-__bfloat162float(hh[3])));
    size_t tb = ((size_t)((b*8 + (n>>7))*32 + (k0>>5)))*8192;
    uint32_t off = swz64(n & 127, k4 >> 3) + ((k4 >> 2) & 1)*8;
    *(uint2*)((char*)g_XTH + tb + off) = hp;
    *(uint2*)((char*)g_XTL + tb + off) = lp;
  }
}

// ===========================================================================
// mma.sync GEMM: 256m x 128n per CTA, K=1024, bf16x3, BK=64 bulk-fed.
// 256 threads, 8 warps (4m x 2n), warp tile 64x64.
// MODE 0: A=Weff (M=3072), B=XT; each CTA's m-tile is pure Q, K or V.
// MODE 1: A=Wproj, B=OT -> ACCUMULATE into final output (+bias via dwconv).
// ===========================================================================
#define GSTG 98304u
#define GEMM_SMEM (1024u + 2u*GSTG)

template<int MODE>
__global__ __launch_bounds__(256, 1) void gemm_mma(const float* __restrict__ bias,
                                                   float* __restrict__ outp){
  extern __shared__ char smem[];
  const uint32_t sb = smem_u32(smem);
  const int tid = threadIdx.x;
  const int wid = tid >> 5, lane = tid & 31;
  const int mt = blockIdx.x;
  const int b  = blockIdx.y >> 3;
  const int nt = blockIdx.y & 7;
  const int m0 = mt*256, n0 = nt*128;
  const int wm = (wid >> 1) * 64;
  const int wn = (wid & 1) * 64;

  const char* Ahb = (const char*)(MODE==0 ? g_WeffH : g_WprojH) + (size_t)mt*32*16384;
  const char* Alb = (const char*)(MODE==0 ? g_WeffL : g_WprojL) + (size_t)mt*32*16384;
  const char* Bhb = (const char*)(MODE==0 ? g_XTH : g_OTH) + (size_t)((b*8+nt)*32)*8192;
  const char* Blb = (const char*)(MODE==0 ? g_XTL : g_OTL) + (size_t)((b*8+nt)*32)*8192;

  if (tid == 0){ MBARRIER_INIT(sb+8, 1); MBARRIER_INIT(sb+16, 1); }
  __syncthreads();

  float acc[4][8][4];
  #pragma unroll
  for (int i=0;i<4;i++)
    #pragma unroll
    for (int j=0;j<8;j++)
      #pragma unroll
      for (int r=0;r<4;r++) acc[i][j][r] = 0.f;

  auto issue = [&](int kt2){
    if (tid == 0){
      int buf = kt2 & 1;
      uint32_t mb = sb + 8 + buf*8;
      MBARRIER_EXPECT_TX(mb, GSTG);
      uint32_t d = sb + 1024 + buf*GSTG;
      BULKCP(d,         Ahb + (size_t)kt2*32768, 32768, mb);
      BULKCP(d+32768,   Alb + (size_t)kt2*32768, 32768, mb);
      BULKCP(d+65536,   Bhb + (size_t)kt2*16384, 16384, mb);
      BULKCP(d+81920,   Blb + (size_t)kt2*16384, 16384, mb);
    }
  };

  issue(0);
  for (int kt2 = 0; kt2 < 16; kt2++){
    if (kt2 + 1 < 16) issue(kt2+1);
    MBARRIER_WAIT_PARITY(sb + 8 + (kt2&1)*8, (kt2>>1)&1);
    const uint32_t st = sb + 1024 + (kt2&1)*GSTG;

    #pragma unroll
    for (int s = 0; s < 2; s++){
      const uint32_t Ah = st + s*16384;
      const uint32_t Bh = st + 65536 + s*8192;
      #pragma unroll
      for (int ks = 0; ks < 2; ks++){
        uint32_t ah[4][4], al[4][4], bh[8][2], bl[8][2];
        #pragma unroll
        for (int mi = 0; mi < 4; mi++){
          uint32_t row = wm + mi*16 + (lane & 15);
          uint32_t c16 = ks*2 + (lane >> 4);
          uint32_t addr = Ah + swz64(row, c16);
          ldm4(ah[mi], addr);
          ldm4(al[mi], addr + 32768);     // Al tile = Ah + 32768 (same s)
        }
        #pragma unroll
        for (int np = 0; np < 4; np++){
          uint32_t row = wn + np*16 + (lane >> 4)*8 + (lane & 7);
          uint32_t c16 = ks*2 + ((lane >> 3) & 1);
          uint32_t addr = Bh + swz64(row, c16);
          uint32_t r[4];
          ldm4(r, addr);
          bh[np*2][0]=r[0]; bh[np*2][1]=r[1]; bh[np*2+1][0]=r[2]; bh[np*2+1][1]=r[3];
          ldm4(r, addr + 16384);           // Bl tile = Bh + 16384 (same s)
          bl[np*2][0]=r[0]; bl[np*2][1]=r[1]; bl[np*2+1][0]=r[2]; bl[np*2+1][1]=r[3];
        }
        #pragma unroll
        for (int mi=0;mi<4;mi++)
          #pragma unroll
          for (int ni=0;ni<8;ni++) mma16816(acc[mi][ni], ah[mi], bh[ni]);
        #pragma unroll
        for (int mi=0;mi<4;mi++)
          #pragma unroll
          for (int ni=0;ni<8;ni++) mma16816(acc[mi][ni], ah[mi], bl[ni]);
        #pragma unroll
        for (int mi=0;mi<4;mi++)
          #pragma unroll
          for (int ni=0;ni<8;ni++) mma16816(acc[mi][ni], al[mi], bh[ni]);
      }
    }
    __syncthreads();
  }

  if (MODE == 1){
    // final output: out[(b, cch, qc, n)] += acc  (dwconv wrote conv+bias_pe;
    // proj bias added here)
    #pragma unroll
    for (int mi=0;mi<4;mi++)
      #pragma unroll
      for (int half=0; half<2; half++){
        int gm = m0 + wm + mi*16 + (lane >> 2) + half*8;
        float bi = bias[gm];
        int qc = gm >> 8; int cch = gm & 255;
        float* dst = outp + ((size_t)((b*CC + cch)*4 + qc))*NPIX;
        #pragma unroll
        for (int ni=0;ni<8;ni++){
          int nn = n0 + wn + ni*8 + (lane & 3)*2;
          float2 old = *(float2*)&dst[nn];
          float2 v = make_float2(old.x + acc[mi][ni][half*2+0] + bi,
                                 old.y + acc[mi][ni][half*2+1] + bi);
          *(float2*)&dst[nn] = v;
        }
      }
    return;
  }

  // ---- MODE 0 epilogue: region = Q(0) / K(1) / V(2) ----
  const int region = mt % 3;
  const int qc = mt / 3;
  if (region == 2){
    // V: direct hi/lo stores into (d, n) tiles
    #pragma unroll
    for (int mi=0;mi<4;mi++)
      #pragma unroll
      for (int half=0; half<2; half++){
        int gm = m0 + wm + mi*16 + (lane >> 2) + half*8;
        float bi = bias[gm];
        int o = gm - qc*768; int cch = o & 255;
        int ch = (qc << 8) | cch; int hh = ch >> 7; int dd = ch & 127;
        size_t bhbase = ((size_t)(b*HEADS + hh))*16*16384;
        #pragma unroll
        for (int ni=0;ni<8;ni++){
          int nn = n0 + wn + ni*8 + (lane & 3)*2;
          float v0 = acc[mi][ni][half*2+0] + bi;
          float v1 = acc[mi][ni][half*2+1] + bi;
          __nv_bfloat16 h0 = __float2bfloat16(v0), h1 = __float2bfloat16(v1);
          size_t tb = bhbase + (size_t)(nn>>6)*16384;
          uint32_t off = swz128(dd, (nn&63)>>3) + (nn&7)*2;
          *(uint32_t*)((char*)g_VH + tb + off) =
              pkbf2(__bfloat162float(h0), __bfloat162float(h1));
          *(uint32_t*)((char*)g_VL + tb + off) =
              pkbf2(v0-__bfloat162float(h0), v1-__bfloat162float(h1));
        }
      }
  } else {
    // Q/K: stage fp32 into smem (scale folded), transpose, emit (n,d) tiles
    float* T = (float*)(smem + 1024);   // 256 x 132 fp32 = 135168 B
    const float scl = (region == 0) ? 0.12751875542484462f  // qscale*log2e
                                    : 1.f;
    #pragma unroll
    for (int mi=0;mi<4;mi++)
      #pragma unroll
      for (int half=0; half<2; half++){
        int gm = m0 + wm + mi*16 + (lane >> 2) + half*8;
        int row = gm - m0;
        float bi = bias[gm];
        #pragma unroll
        for (int ni=0;ni<8;ni++){
          int nn = wn + ni*8 + (lane & 3)*2;
          T[row*132 + nn]     = (acc[mi][ni][half*2+0] + bi)*scl;
          T[row*132 + nn + 1] = (acc[mi][ni][half*2+1] + bi)*scl;
        }
      }
    __syncthreads();

    char* dh = (region == 0) ? (char*)g_QTH : (char*)g_KTH;
    char* dl = (region == 0) ? (char*)g_QTL : (char*)g_KTL;
    const int nl = tid & 127;
    const int hp = tid >> 7;            // head parity within tile
    const int n = n0 + nl;
    const int head = qc*2 + hp;
    const size_t tb = ((size_t)((b*HEADS + head)*16 + (n>>6)))*16384;
    const uint32_t r6 = n & 63;
    #pragma unroll
    for (int c16 = 0; c16 < 16; c16++){
      float a[8]; __nv_bfloat16 h[8]; float hf[8];
      #pragma unroll
      for (int i=0;i<8;i++) a[i] = T[(hp*128 + c16*8 + i)*132 + nl];
      #pragma unroll
      for (int i=0;i<8;i++){ h[i] = __float2bfloat16(a[i]); hf[i] = __bfloat162float(h[i]); }
      uint4 H, L;
      H.x = pkbf2(hf[0],hf[1]); H.y = pkbf2(hf[2],hf[3]);
      H.z = pkbf2(hf[4],hf[5]); H.w = pkbf2(hf[6],hf[7]);
      L.x = pkbf2(a[0]-hf[0], a[1]-hf[1]);
      L.y = pkbf2(a[2]-hf[2], a[3]-hf[3]);
      L.z = pkbf2(a[4]-hf[4], a[5]-hf[5]);
      L.w = pkbf2(a[6]-hf[6], a[7]-hf[7]);
      uint32_t off = swz256(r6, c16);
      *(uint4*)(dh + tb + off) = H;
      *(uint4*)(dl + tb + off) = L;
    }
  }
}

// ===========================================================================
// Flash attention, mma.sync bf16x3, bulk-copy fed.
// CTA = (b,h) x 128 queries, 256 thr, 8 warps x 16 q-rows.
// ===========================================================================
#define ASTG 65536u
#define AT_SMEM (1024u + 2u*ASTG)

__global__ __launch_bounds__(256, 1) void attn_mma(){
  extern __shared__ char smem[];
  const uint32_t sb = smem_u32(smem);
  const int tid = threadIdx.x;
  const int wid = tid >> 5, lane = tid & 31;
  const int bh = blockIdx.y;
  const int qi = blockIdx.x;           // q block of 128
  const int q0 = qi * 128;
  const int b = bh >> 3, h = bh & 7;

  if (tid == 0){
    MBARRIER_INIT(sb+8, 1); MBARRIER_INIT(sb+16, 1); MBARRIER_INIT(sb+24, 1);
  }
  __syncthreads();

  // ---- Q load: 2 tiles hi + 2 tiles lo = 64KB into stage0 region
  if (tid == 0){
    MBARRIER_EXPECT_TX(sb+24, 65536);
    const char* qh_g = (const char*)g_QTH + ((size_t)bh*16 + qi*2)*16384;
    const char* ql_g = (const char*)g_QTL + ((size_t)bh*16 + qi*2)*16384;
    BULKCP(sb+1024,         qh_g, 32768, sb+24);
    BULKCP(sb+1024+32768,   ql_g, 32768, sb+24);
  }
  MBARRIER_WAIT_PARITY(sb+24, 0);

  uint32_t qfh[8][4], qfl[8][4];
  {
    uint32_t row = wid*16 + (lane & 15);
    uint32_t base = sb + 1024 + (row >> 6)*16384;
    uint32_t r6 = row & 63;
    #pragma unroll
    for (int kf = 0; kf < 8; kf++){
      uint32_t c16 = kf*2 + (lane >> 4);
      uint32_t addr = base + swz256(r6, c16);
      ldm4(qfh[kf], addr);
      ldm4(qfl[kf], addr + 32768);
    }
  }
  __syncthreads();   // Q consumed; stage0 reusable

  const char* kh_g = (const char*)g_KTH + (size_t)bh*16*16384;
  const char* kl_g = (const char*)g_KTL + (size_t)bh*16*16384;
  const char* vh_g = (const char*)g_VH  + (size_t)bh*16*16384;
  const char* vl_g = (const char*)g_VL  + (size_t)bh*16*16384;

  auto issueKV = [&](int kb){
    if (tid == 0){
      int buf = kb & 1;
      uint32_t mb = sb + 8 + buf*8;
      MBARRIER_EXPECT_TX(mb, ASTG);
      uint32_t d = sb + 1024 + buf*ASTG;
      BULKCP(d,         kh_g + (size_t)kb*16384, 16384, mb);
      BULKCP(d+16384,   kl_g + (size_t)kb*16384, 16384, mb);
      BULKCP(d+32768,   vh_g + (size_t)kb*16384, 16384, mb);
      BULKCP(d+49152,   vl_g + (size_t)kb*16384, 16384, mb);
    }
  };

  float accO[16][4];
  #pragma unroll
  for (int i=0;i<16;i++)
    #pragma unroll
    for (int r=0;r<4;r++) accO[i][r] = 0.f;
  float m0r = -1e30f, m1r = -1e30f, l0 = 0.f, l1 = 0.f;

  issueKV(0);
  for (int kb = 0; kb < 16; kb++){
    if (kb + 1 < 16) issueKV(kb+1);
    MBARRIER_WAIT_PARITY(sb + 8 + (kb&1)*8, (kb>>1)&1);
    const uint32_t st = sb + 1024 + (kb&1)*ASTG;

    // ---- S = Q K^T  (16q x 64k per warp), bf16x3
    float S[8][4];
    #pragma unroll
    for (int i=0;i<8;i++)
      #pragma unroll
      for (int r=0;r<4;r++) S[i][r] = 0.f;
    #pragma unroll
    for (int kf = 0; kf < 8; kf++){
      #pragma unroll
      for (int np = 0; np < 4; np++){
        uint32_t row = np*16 + (lane >> 4)*8 + (lane & 7);
        uint32_t c16 = kf*2 + ((lane >> 3) & 1);
        uint32_t addr = st + swz256(row, c16);
        uint32_t r[4];
        ldm4(r, addr);
        uint32_t b0[2] = {r[0], r[1]}, b1[2] = {r[2], r[3]};
        mma16816(S[np*2],   qfh[kf], b0);
        mma16816(S[np*2+1], qfh[kf], b1);
        mma16816(S[np*2],   qfl[kf], b0);
        mma16816(S[np*2+1], qfl[kf], b1);
        ldm4(r, addr + 16384);
        uint32_t c0[2] = {r[0], r[1]}, c1[2] = {r[2], r[3]};
        mma16816(S[np*2],   qfh[kf], c0);
        mma16816(S[np*2+1], qfh[kf], c1);
      }
    }

    // ---- online softmax (log2 domain; log2e folded into Q)
    float mx0 = -1e30f, mx1 = -1e30f;
    #pragma unroll
    for (int i=0;i<8;i++){
      mx0 = fmaxf(mx0, fmaxf(S[i][0], S[i][1]));
      mx1 = fmaxf(mx1, fmaxf(S[i][2], S[i][3]));
    }
    mx0 = fmaxf(mx0, __shfl_xor_sync(0xffffffffu, mx0, 1));
    mx0 = fmaxf(mx0, __shfl_xor_sync(0xffffffffu, mx0, 2));
    mx1 = fmaxf(mx1, __shfl_xor_sync(0xffffffffu, mx1, 1));
    mx1 = fmaxf(mx1, __shfl_xor_sync(0xffffffffu, mx1, 2));
    float mn0 = fmaxf(m0r, mx0), mn1 = fmaxf(m1r, mx1);
    float al0 = exp2f(m0r - mn0), al1 = exp2f(m1r - mn1);
    m0r = mn0; m1r = mn1;

    float rs0 = 0.f, rs1 = 0.f;
    uint32_t ph[4][4], pl[4][4];
    #pragma unroll
    for (int nf = 0; nf < 8; nf++){
      float p0 = exp2f(S[nf][0] - mn0);
      float p1 = exp2f(S[nf][1] - mn0);
      float p2 = exp2f(S[nf][2] - mn1);
      float p3 = exp2f(S[nf][3] - mn1);
      rs0 += p0 + p1; rs1 += p2 + p3;
      __nv_bfloat16 h0 = __float2bfloat16(p0), h1 = __float2bfloat16(p1);
      __nv_bfloat16 h2 = __float2bfloat16(p2), h3 = __float2bfloat16(p3);
      int kf = nf >> 1, pc = (nf & 1)*2;
      ph[kf][pc+0] = pkbf2(__bfloat162float(h0), __bfloat162float(h1));
      ph[kf][pc+1] = pkbf2(__bfloat162float(h2), __bfloat162float(h3));
      pl[kf][pc+0] = pkbf2(p0-__bfloat162float(h0), p1-__bfloat162float(h1));
      pl[kf][pc+1] = pkbf2(p2-__bfloat162float(h2), p3-__bfloat162float(h3));
    }
    rs0 += __shfl_xor_sync(0xffffffffu, rs0, 1);
    rs0 += __shfl_xor_sync(0xffffffffu, rs0, 2);
    rs1 += __shfl_xor_sync(0xffffffffu, rs1, 1);
    rs1 += __shfl_xor_sync(0xffffffffu, rs1, 2);
    l0 = l0*al0 + rs0; l1 = l1*al1 + rs1;

    #pragma unroll
    for (int i=0;i<16;i++){
      accO[i][0] *= al0; accO[i][1] *= al0;
      accO[i][2] *= al1; accO[i][3] *= al1;
    }

    // ---- accO += P V  (16q x 128d per warp), bf16x3
    const uint32_t vb = st + 32768;
    #pragma unroll
    for (int kf = 0; kf < 4; kf++){
      #pragma unroll
      for (int np = 0; np < 8; np++){
        uint32_t row = np*16 + (lane >> 4)*8 + (lane & 7);
        uint32_t c16 = kf*2 + ((lane >> 3) & 1);
        uint32_t addr = vb + swz128(row, c16);
        uint32_t r[4];
        ldm4(r, addr);
        uint32_t b0[2] = {r[0], r[1]}, b1[2] = {r[2], r[3]};
        mma16816(accO[np*2],   ph[kf], b0);
        mma16816(accO[np*2+1], ph[kf], b1);
        mma16816(accO[np*2],   pl[kf], b0);
        mma16816(accO[np*2+1], pl[kf], b1);
        ldm4(r, addr + 16384);
        uint32_t c0[2] = {r[0], r[1]}, c1[2] = {r[2], r[3]};
        mma16816(accO[np*2],   ph[kf], c0);
        mma16816(accO[np*2+1], ph[kf], c1);
      }
    }
    __syncthreads();
  }

  // ---- epilogue: O/l -> bf16 hi/lo into tiled OT
  float inv0 = 1.f / l0, inv1 = 1.f / l1;
  int na = q0 + wid*16 + (lane >> 2);
  int nb2 = na + 8;
  #pragma unroll
  for (int nf = 0; nf < 16; nf++){
    int ch = h*HD + nf*8 + (lane & 3)*2;
    float v0 = accO[nf][0]*inv0, v1 = accO[nf][1]*inv0;
    float v2 = accO[nf][2]*inv1, v3 = accO[nf][3]*inv1;
    __nv_bfloat16 h0 = __float2bfloat16(v0), h1 = __float2bfloat16(v1);
    __nv_bfloat16 h2 = __float2bfloat16(v2), h3 = __float2bfloat16(v3);
    size_t tba = ((size_t)((b*8 + (na>>7))*32 + (ch>>5)))*8192;
    size_t tbb = ((size_t)((b*8 + (nb2>>7))*32 + (ch>>5)))*8192;
    uint32_t ofa = swz64(na & 127, (ch>>3)&3) + (ch&7)*2;
    uint32_t ofb = swz64(nb2 & 127, (ch>>3)&3) + (ch&7)*2;
    *(uint32_t*)((char*)g_OTH + tba + ofa) = pkbf2(__bfloat162float(h0), __bfloat162float(h1));
    *(uint32_t*)((char*)g_OTL + tba + ofa) = pkbf2(v0-__bfloat162float(h0), v1-__bfloat162float(h1));
    *(uint32_t*)((char*)g_OTH + tbb + ofb) = pkbf2(__bfloat162float(h2), __bfloat162float(h3));
    *(uint32_t*)((char*)g_OTL + tbb + ofb) = pkbf2(v2-__bfloat162float(h2), v3-__bfloat162float(h3));
  }
}

// ---------------------------------------------------------------------------
// Quaternion depthwise 3x3. WRITES (=) conv + pe-bias to output; proj GEMM
// accumulates on top. Runs on a side stream concurrent with GEMM1/attention.
// ---------------------------------------------------------------------------
__global__ __launch_bounds__(256) void qdwconv_kernel(const float* __restrict__ x,
                                                      const float* __restrict__ w_pe,
                                                      const float* __restrict__ b_pe,
                                                      float* __restrict__ outp){
  __shared__ float xs[4][1024];
  __shared__ float wt[4][4][9];
  const int bid = blockIdx.x;
  const int c = bid & 255, b = bid >> 8;
  const int tid = threadIdx.x;

  #pragma unroll
  for (int p=0;p<4;p++){
    const float* xp = x + ((size_t)((b*CC + c)*4 + p))*NPIX;
    for (int k=tid; k<1024; k+=256) xs[p][k] = xp[k];
  }
  if (tid < 144){
    int qc = tid/36, p = (tid/9)&3, t = tid%9;
    wt[qc][p][t] = c_SGN[qc*4+p] * w_pe[(c_IDX[qc*4+p]*CC + c)*9 + t];
  }
  __syncthreads();

  float bia[4];
  #pragma unroll
  for (int qc=0;qc<4;qc++) bia[qc] = b_pe[qc*CC + c];

  for (int k=tid; k<1024; k+=256){
    int hh = k >> 5, ww = k & 31;
    float acc[4] = {bia[0],bia[1],bia[2],bia[3]};
    #pragma unroll
    for (int p=0;p<4;p++){
      #pragma unroll
      for (int kh=0;kh<3;kh++){
        int h2 = hh + kh - 1;
        if (h2 < 0 || h2 > 31) continue;
        #pragma unroll
        for (int kw=0;kw<3;kw++){
          int w2 = ww + kw - 1;
          if (w2 < 0 || w2 > 31) continue;
          float xv = xs[p][h2*32 + w2];
          #pragma unroll
          for (int qc=0;qc<4;qc++) acc[qc] = fmaf(wt[qc][p][kh*3+kw], xv, acc[qc]);
        }
      }
    }
    #pragma unroll
    for (int qc=0;qc<4;qc++)
      outp[((size_t)((b*CC + c)*4 + qc))*NPIX + k] = acc[qc];
  }
}

// ---------------------------------------------------------------------------
extern "C" void kernel_launch(void* const* d_in, const int* in_sizes, int n_in,
                              void* d_out, int out_size){
  const float* x      = (const float*)d_in[0];
  const float* w_qkv  = (const float*)d_in[1];
  const float* b_qkv  = (const float*)d_in[2];
  const float* w_proj = (const float*)d_in[3];
  const float* b_proj = (const float*)d_in[4];
  const float* w_pe   = (const float*)d_in[5];
  const float* b_pe   = (const float*)d_in[6];
  float* outp = (float*)d_out;

  (void)in_sizes; (void)n_in; (void)out_size;

  static cudaStream_t s2 = nullptr;
  static cudaEvent_t eFork = nullptr, eJoin = nullptr;
  if (s2 == nullptr){
    cudaStreamCreateWithFlags(&s2, cudaStreamNonBlocking);
    cudaEventCreateWithFlags(&eFork, cudaEventDisableTiming);
    cudaEventCreateWithFlags(&eJoin, cudaEventDisableTiming);
  }

  cudaFuncSetAttribute(gemm_mma<0>, cudaFuncAttributeMaxDynamicSharedMemorySize,
                       GEMM_SMEM);
  cudaFuncSetAttribute(gemm_mma<1>, cudaFuncAttributeMaxDynamicSharedMemorySize,
                       GEMM_SMEM);
  cudaFuncSetAttribute(attn_mma, cudaFuncAttributeMaxDynamicSharedMemorySize,
                       AT_SMEM);

  // ---- fork: dwconv runs on side stream, concurrent with the main chain ----
  cudaEventRecord(eFork, 0);
  cudaStreamWaitEvent(s2, eFork, 0);
  qdwconv_kernel<<< NB*CC, 256, 0, s2 >>>(x, w_pe, b_pe, outp);
  cudaEventRecord(eJoin, s2);

  // ---- main chain ----
  __nv_bfloat16 *weffH, *weffL, *wprojH, *wprojL;
  cudaGetSymbolAddress((void**)&weffH, g_WeffH);
  cudaGetSymbolAddress((void**)&weffL, g_WeffL);
  cudaGetSymbolAddress((void**)&wprojH, g_WprojH);
  cudaGetSymbolAddress((void**)&wprojL, g_WprojL);
  prep_w_kernel<<< MQKV*128/256, 256 >>>(w_qkv, weffH, weffL, 1);
  prep_w_kernel<<< DIM*128/256, 256 >>>(w_proj, wprojH, wprojL, 0);
  prep_xt_kernel<<< dim3(32,32,8), 256 >>>(x);

  // QKV GEMM: emits Q/K (n,d) and V (d,n) bf16 hi/lo tiles directly
  gemm_mma<0><<< dim3(12,64), 256, GEMM_SMEM >>>(b_qkv, nullptr);

  // Attention: mma.sync flash, 8 q-tiles x 64 (b,h)
  attn_mma<<< dim3(8,64), 256, AT_SMEM >>>();

  // ---- join: dwconv output must be in place before proj accumulates ----
  cudaStreamWaitEvent(0, eJoin, 0);

  // Proj: (1024 x 8192) mma.sync bf16x3 -> accumulate into final output
  gemm_mma<1><<< dim3(4,64), 256, GEMM_SMEM >>>(b_proj, outp);
}

// round 10
// speedup vs baseline: 1.1522x; 1.1133x over previous
#include <cuda_runtime.h>
#include <cuda_bf16.h>
#include <cuda_fp16.h>
#include <cstdint>
#include <math.h>

#define NB 8
#define CC 256
#define NPIX 1024
#define HEADS 8
#define HD 128
#define MQKV 3072
#define DIM 1024

// Hamilton tables
__constant__ int   c_IDX[16] = {0,1,2,3, 1,0,3,2, 2,3,0,1, 3,2,1,0};
__constant__ float c_SGN[16] = {1.f,-1.f,-1.f,-1.f, 1.f,1.f,1.f,-1.f,
                                1.f,-1.f,1.f,1.f, 1.f,1.f,-1.f,1.f};

// Scratch (device globals). ALL tensor-core operands pre-tiled + pre-swizzled
// so kernels fetch whole tiles with single cp.async.bulk copies.
__device__ __nv_bfloat16 g_WeffH[(size_t)MQKV*DIM];     // bf16 hi
__device__ __nv_bfloat16 g_WeffL[(size_t)MQKV*DIM];     // bf16 lo
__device__ __half        g_WprojH[(size_t)DIM*DIM];     // fp16 (hi only)
__device__ __nv_bfloat16 g_XTH[(size_t)NB*NPIX*DIM];    // bf16 hi
__device__ __nv_bfloat16 g_XTL[(size_t)NB*NPIX*DIM];    // bf16 lo
__device__ __half g_OTH[(size_t)NB*NPIX*DIM];           // fp16 hi
__device__ __half g_OTL[(size_t)NB*NPIX*DIM];           // fp16 lo (residual)
__device__ __nv_bfloat16 g_QTH[(size_t)NB*HEADS*NPIX*HD];
__device__ __nv_bfloat16 g_QTL[(size_t)NB*HEADS*NPIX*HD];
__device__ __nv_bfloat16 g_KTH[(size_t)NB*HEADS*NPIX*HD];
__device__ __nv_bfloat16 g_KTL[(size_t)NB*HEADS*NPIX*HD];
__device__ __half g_VH[(size_t)NB*HEADS*HD*NPIX];       // fp16 (hi only)

// ===========================================================================
// Helpers (base-ISA: cp.async.bulk / mbarrier / ldmatrix / mma.sync)
// ===========================================================================
__device__ __forceinline__ uint32_t smem_u32(const void* p){
  uint32_t a;
  asm("{ .reg .u64 t; cvta.to.shared.u64 t, %1; cvt.u32.u64 %0, t; }"
      : "=r"(a) : "l"(p));
  return a;
}
__device__ __forceinline__ void ldm4(uint32_t r[4], uint32_t addr){
  asm volatile("ldmatrix.sync.aligned.m8n8.x4.shared.b16 {%0,%1,%2,%3}, [%4];"
    : "=r"(r[0]),"=r"(r[1]),"=r"(r[2]),"=r"(r[3]) : "r"(addr));
}
__device__ __forceinline__ void mma16816(float c[4], const uint32_t a[4],
                                         const uint32_t b[2]){
  asm volatile(
    "mma.sync.aligned.m16n8k16.row.col.f32.bf16.bf16.f32 "
    "{%0,%1,%2,%3}, {%4,%5,%6,%7}, {%8,%9}, {%0,%1,%2,%3};"
    : "+f"(c[0]),"+f"(c[1]),"+f"(c[2]),"+f"(c[3])
    : "r"(a[0]),"r"(a[1]),"r"(a[2]),"r"(a[3]), "r"(b[0]),"r"(b[1]));
}
__device__ __forceinline__ void mma16816h(float c[4], const uint32_t a[4],
                                          const uint32_t b[2]){
  asm volatile(
    "mma.sync.aligned.m16n8k16.row.col.f32.f16.f16.f32 "
    "{%0,%1,%2,%3}, {%4,%5,%6,%7}, {%8,%9}, {%0,%1,%2,%3};"
    : "+f"(c[0]),"+f"(c[1]),"+f"(c[2]),"+f"(c[3])
    : "r"(a[0]),"r"(a[1]),"r"(a[2]),"r"(a[3]), "r"(b[0]),"r"(b[1]));
}
__device__ __forceinline__ uint32_t pkbf2(float a, float b){
  __nv_bfloat162 t = __floats2bfloat162_rn(a, b);
  return *(uint32_t*)&t;
}
__device__ __forceinline__ uint32_t pkhf2(float a, float b){
  __half2 t = __floats2half2_rn(a, b);
  return *(uint32_t*)&t;
}
#define BULKCP(dst, src, bytes, mb) \
  asm volatile("cp.async.bulk.shared::cluster.global.mbarrier::complete_tx::bytes [%0], [%1], %2, [%3];" \
    :: "r"((uint32_t)(dst)), "l"(src), "r"((uint32_t)(bytes)), "r"((uint32_t)(mb)) : "memory")
#define MBARRIER_INIT(mb, c) \
  asm volatile("mbarrier.init.shared.b64 [%0], %1;" :: "r"((uint32_t)(mb)), "r"((uint32_t)(c)) : "memory")
#define MBARRIER_EXPECT_TX(mb, tx) \
  asm volatile("mbarrier.arrive.expect_tx.shared.b64 _, [%0], %1;" :: "r"((uint32_t)(mb)), "r"((uint32_t)(tx)) : "memory")
#define MBARRIER_WAIT_PARITY(mb, ph) do { \
    uint32_t _m = (uint32_t)(mb); uint32_t _p = (uint32_t)(ph); uint32_t _d; \
    asm volatile("{\n\t.reg .pred p;\n\t" \
        "mbarrier.try_wait.parity.acquire.cta.shared::cta.b64 p, [%1], %2;\n\t" \
        "selp.b32 %0, 1, 0, p;\n\t}" : "=r"(_d) : "r"(_m), "r"(_p) : "memory"); \
    if (!_d) { \
      asm volatile("{\n\t.reg .pred P1;\n\t" \
        "WL_%=:\n\t" \
        "mbarrier.try_wait.parity.acquire.cta.shared::cta.b64 P1, [%0], %1, 0x989680;\n\t" \
        "@P1 bra.uni WD_%=;\n\t" \
        "bra.uni WL_%=;\n\t" \
        "WD_%=:\n\t}" :: "r"(_m), "r"(_p) : "memory"); \
    } \
  } while(0)

// swizzled byte offsets inside tiles (row-major rows of 64/128/256 bytes)
__device__ __forceinline__ uint32_t swz64 (uint32_t r, uint32_t c16){ return r*64u  + ((c16 ^ ((r>>1)&3u))<<4); }
__device__ __forceinline__ uint32_t swz128(uint32_t r, uint32_t c16){ return r*128u + ((c16 ^ (r&7u))<<4); }
__device__ __forceinline__ uint32_t swz256(uint32_t r, uint32_t c16){ return r*256u + ((c16 ^ (r&7u))<<4); }

// ===========================================================================
// Prep: Hamilton-folded weights. QKV: bf16 hi/lo. Proj: fp16 hi only.
// ===========================================================================
__global__ void prep_w_kernel(const float* __restrict__ w,
                              char* __restrict__ outH,
                              char* __restrict__ outL, int is_qkv){
  int idx = blockIdx.x*256 + threadIdx.x;     // chunk id: M*128
  int g = idx >> 7, c = idx & 127;            // c = 16B chunk along k
  int k0 = c*8;
  int qc, o;
  if (is_qkv){ qc = g / 768; o = g - qc*768; } else { qc = g >> 8; o = g & 255; }
  int p = k0 >> 8, cch = k0 & 255;
  float s = c_SGN[qc*4+p];
  const float* src = w + ((size_t)(c_IDX[qc*4+p]*(is_qkv?768:256) + o))*256 + cch;
  float4 v0 = *(const float4*)src;
  float4 v1 = *(const float4*)(src+4);
  float a[8] = {v0.x*s,v0.y*s,v0.z*s,v0.w*s, v1.x*s,v1.y*s,v1.z*s,v1.w*s};
  size_t base = ((size_t)((g>>8)*32 + (c>>2)))*16384;
  uint32_t off = swz64(g & 255, c & 3);
  if (is_qkv){
    __nv_bfloat16 h[8]; float hf[8];
    #pragma unroll
    for (int i=0;i<8;i++){ h[i] = __float2bfloat16(a[i]); hf[i] = __bfloat162float(h[i]); }
    uint4 H, L;
    H.x = pkbf2(hf[0],hf[1]); H.y = pkbf2(hf[2],hf[3]);
    H.z = pkbf2(hf[4],hf[5]); H.w = pkbf2(hf[6],hf[7]);
    L.x = pkbf2(a[0]-hf[0], a[1]-hf[1]);
    L.y = pkbf2(a[2]-hf[2], a[3]-hf[3]);
    L.z = pkbf2(a[4]-hf[4], a[5]-hf[5]);
    L.w = pkbf2(a[6]-hf[6], a[7]-hf[7]);
    *(uint4*)(outH + base + off) = H;
    *(uint4*)(outL + base + off) = L;
  } else {
    uint4 H;
    H.x = pkhf2(a[0],a[1]); H.y = pkhf2(a[2],a[3]);
    H.z = pkhf2(a[4],a[5]); H.w = pkhf2(a[6],a[7]);
    *(uint4*)(outH + base + off) = H;
  }
}

// x (b, cch, p, n) fp32 -> XT tiles (b, ntile, kt) bf16 hi/lo
__global__ void prep_xt_kernel(const float* __restrict__ x){
  __shared__ float sm[32][33];
  int b = blockIdx.z, k0 = blockIdx.x*32, n0 = blockIdx.y*32;
  int t = threadIdx.x;
  {
    int kk = t >> 3, n4 = (t & 7) << 2;
    int k = k0 + kk; int p = k >> 8, cch = k & 255;
    float4 v = *(const float4*)&x[((size_t)((b*CC+cch)*4 + p))*NPIX + n0 + n4];
    sm[kk][n4] = v.x; sm[kk][n4+1] = v.y; sm[kk][n4+2] = v.z; sm[kk][n4+3] = v.w;
  }
  __syncthreads();
  {
    int nn = t >> 3, k4 = (t & 7) << 2;
    int n = n0 + nn;
    float a[4];
    #pragma unroll
    for (int i=0;i<4;i++) a[i] = sm[k4+i][nn];
    __nv_bfloat16 hh[4];
    #pragma unroll
    for (int i=0;i<4;i++) hh[i] = __float2bfloat16(a[i]);
    uint2 hp = make_uint2(pkbf2(__bfloat162float(hh[0]), __bfloat162float(hh[1])),
                          pkbf2(__bfloat162float(hh[2]), __bfloat162float(hh[3])));
    uint2 lp = make_uint2(pkbf2(a[0]-__bfloat162float(hh[0]), a[1]-__bfloat162float(hh[1])),
                          pkbf2(a[2]-__bfloat162float(hh[2]), a[3]-__bfloat162float(hh[3])));
    size_t tb = ((size_t)((b*8 + (n>>7))*32 + (k0>>5)))*8192;
    uint32_t off = swz64(n & 127, k4 >> 3) + ((k4 >> 2) & 1)*8;
    *(uint2*)((char*)g_XTH + tb + off) = hp;
    *(uint2*)((char*)g_XTL + tb + off) = lp;
  }
}

// ===========================================================================
// mma.sync GEMM: 256m x 128n per CTA, K=1024, BK=64 bulk-fed.
// MODE 0: bf16x3. A=Weff, B=XT. Fused epilogue -> Q/K bf16 tiles, V fp16.
// MODE 1: fp16x2. A=Wproj fp16 (hi only), B=OT fp16 hi/lo. Accumulates out.
// ===========================================================================
#define GSTG0 98304u
#define GSTG1 65536u
#define GEMM_SMEM0 (1024u + 2u*GSTG0)
#define GEMM_SMEM1 (1024u + 2u*GSTG1)

template<int MODE>
__global__ __launch_bounds__(256, 1) void gemm_mma(const float* __restrict__ bias,
                                                   float* __restrict__ outp){
  extern __shared__ char smem[];
  const uint32_t sb = smem_u32(smem);
  const int tid = threadIdx.x;
  const int wid = tid >> 5, lane = tid & 31;
  const int mt = blockIdx.x;
  const int b  = blockIdx.y >> 3;
  const int nt = blockIdx.y & 7;
  const int m0 = mt*256, n0 = nt*128;
  const int wm = (wid >> 1) * 64;
  const int wn = (wid & 1) * 64;
  constexpr uint32_t GSTG = (MODE==0) ? GSTG0 : GSTG1;

  const char* Ahb = (const char*)(MODE==0 ? (void*)g_WeffH : (void*)g_WprojH) + (size_t)mt*32*16384;
  const char* Alb = (const char*)g_WeffL + (size_t)mt*32*16384;   // MODE0 only
  const char* Bhb = (const char*)(MODE==0 ? (void*)g_XTH : (void*)g_OTH) + (size_t)((b*8+nt)*32)*8192;
  const char* Blb = (const char*)(MODE==0 ? (void*)g_XTL : (void*)g_OTL) + (size_t)((b*8+nt)*32)*8192;

  if (tid == 0){ MBARRIER_INIT(sb+8, 1); MBARRIER_INIT(sb+16, 1); }
  __syncthreads();

  float acc[4][8][4];
  #pragma unroll
  for (int i=0;i<4;i++)
    #pragma unroll
    for (int j=0;j<8;j++)
      #pragma unroll
      for (int r=0;r<4;r++) acc[i][j][r] = 0.f;

  auto issue = [&](int kt2){
    if (tid == 0){
      int buf = kt2 & 1;
      uint32_t mb = sb + 8 + buf*8;
      MBARRIER_EXPECT_TX(mb, GSTG);
      uint32_t d = sb + 1024 + buf*GSTG;
      if (MODE == 0){
        BULKCP(d,         Ahb + (size_t)kt2*32768, 32768, mb);
        BULKCP(d+32768,   Alb + (size_t)kt2*32768, 32768, mb);
        BULKCP(d+65536,   Bhb + (size_t)kt2*16384, 16384, mb);
        BULKCP(d+81920,   Blb + (size_t)kt2*16384, 16384, mb);
      } else {
        BULKCP(d,         Ahb + (size_t)kt2*32768, 32768, mb);
        BULKCP(d+32768,   Bhb + (size_t)kt2*16384, 16384, mb);
        BULKCP(d+49152,   Blb + (size_t)kt2*16384, 16384, mb);
      }
    }
  };

  issue(0);
  for (int kt2 = 0; kt2 < 16; kt2++){
    if (kt2 + 1 < 16) issue(kt2+1);
    MBARRIER_WAIT_PARITY(sb + 8 + (kt2&1)*8, (kt2>>1)&1);
    const uint32_t st = sb + 1024 + (kt2&1)*GSTG;

    #pragma unroll
    for (int s = 0; s < 2; s++){
      const uint32_t Ah = st + s*16384;
      const uint32_t Bh = (MODE==0 ? st + 65536 : st + 32768) + s*8192;
      #pragma unroll
      for (int ks = 0; ks < 2; ks++){
        uint32_t ah[4][4], al[4][4], bh[8][2], bl[8][2];
        #pragma unroll
        for (int mi = 0; mi < 4; mi++){
          uint32_t row = wm + mi*16 + (lane & 15);
          uint32_t c16 = ks*2 + (lane >> 4);
          uint32_t addr = Ah + swz64(row, c16);
          ldm4(ah[mi], addr);
          if (MODE == 0) ldm4(al[mi], addr + 32768);
        }
        #pragma unroll
        for (int np = 0; np < 4; np++){
          uint32_t row = wn + np*16 + (lane >> 4)*8 + (lane & 7);
          uint32_t c16 = ks*2 + ((lane >> 3) & 1);
          uint32_t addr = Bh + swz64(row, c16);
          uint32_t r[4];
          ldm4(r, addr);
          bh[np*2][0]=r[0]; bh[np*2][1]=r[1]; bh[np*2+1][0]=r[2]; bh[np*2+1][1]=r[3];
          ldm4(r, addr + 16384);        // Bl tile = Bh + 16384 (same s)
          bl[np*2][0]=r[0]; bl[np*2][1]=r[1]; bl[np*2+1][0]=r[2]; bl[np*2+1][1]=r[3];
        }
        if (MODE == 0){
          #pragma unroll
          for (int mi=0;mi<4;mi++)
            #pragma unroll
            for (int ni=0;ni<8;ni++) mma16816(acc[mi][ni], ah[mi], bh[ni]);
          #pragma unroll
          for (int mi=0;mi<4;mi++)
            #pragma unroll
            for (int ni=0;ni<8;ni++) mma16816(acc[mi][ni], ah[mi], bl[ni]);
          #pragma unroll
          for (int mi=0;mi<4;mi++)
            #pragma unroll
            for (int ni=0;ni<8;ni++) mma16816(acc[mi][ni], al[mi], bh[ni]);
        } else {
          #pragma unroll
          for (int mi=0;mi<4;mi++)
            #pragma unroll
            for (int ni=0;ni<8;ni++) mma16816h(acc[mi][ni], ah[mi], bh[ni]);
          #pragma unroll
          for (int mi=0;mi<4;mi++)
            #pragma unroll
            for (int ni=0;ni<8;ni++) mma16816h(acc[mi][ni], ah[mi], bl[ni]);
        }
      }
    }
    __syncthreads();
  }

  if (MODE == 1){
    // final output: out[(b, cch, qc, n)] += acc + bias  (dwconv pre-wrote)
    #pragma unroll
    for (int mi=0;mi<4;mi++)
      #pragma unroll
      for (int half=0; half<2; half++){
        int gm = m0 + wm + mi*16 + (lane >> 2) + half*8;
        float bi = bias[gm];
        int qc = gm >> 8; int cch = gm & 255;
        float* dst = outp + ((size_t)((b*CC + cch)*4 + qc))*NPIX;
        #pragma unroll
        for (int ni=0;ni<8;ni++){
          int nn = n0 + wn + ni*8 + (lane & 3)*2;
          float2 old = *(float2*)&dst[nn];
          float2 v = make_float2(old.x + acc[mi][ni][half*2+0] + bi,
                                 old.y + acc[mi][ni][half*2+1] + bi);
          *(float2*)&dst[nn] = v;
        }
      }
    return;
  }

  // ---- MODE 0 epilogue: region = Q(0) / K(1) / V(2) ----
  const int region = mt % 3;
  const int qc = mt / 3;
  if (region == 2){
    // V: fp16 hi-only stores into (d, n) tiles
    #pragma unroll
    for (int mi=0;mi<4;mi++)
      #pragma unroll
      for (int half=0; half<2; half++){
        int gm = m0 + wm + mi*16 + (lane >> 2) + half*8;
        float bi = bias[gm];
        int o = gm - qc*768; int cch = o & 255;
        int ch = (qc << 8) | cch; int hh = ch >> 7; int dd = ch & 127;
        size_t bhbase = ((size_t)(b*HEADS + hh))*16*16384;
        #pragma unroll
        for (int ni=0;ni<8;ni++){
          int nn = n0 + wn + ni*8 + (lane & 3)*2;
          float v0 = acc[mi][ni][half*2+0] + bi;
          float v1 = acc[mi][ni][half*2+1] + bi;
          size_t tb = bhbase + (size_t)(nn>>6)*16384;
          uint32_t off = swz128(dd, (nn&63)>>3) + (nn&7)*2;
          *(uint32_t*)((char*)g_VH + tb + off) = pkhf2(v0, v1);
        }
      }
  } else {
    // Q/K: stage fp32 into smem (scale folded), transpose, emit (n,d) tiles
    float* T = (float*)(smem + 1024);   // 256 x 132 fp32 = 135168 B
    const float scl = (region == 0) ? 0.12751875542484462f  // qscale*log2e
                                    : 1.f;
    #pragma unroll
    for (int mi=0;mi<4;mi++)
      #pragma unroll
      for (int half=0; half<2; half++){
        int gm = m0 + wm + mi*16 + (lane >> 2) + half*8;
        int row = gm - m0;
        float bi = bias[gm];
        #pragma unroll
        for (int ni=0;ni<8;ni++){
          int nn = wn + ni*8 + (lane & 3)*2;
          T[row*132 + nn]     = (acc[mi][ni][half*2+0] + bi)*scl;
          T[row*132 + nn + 1] = (acc[mi][ni][half*2+1] + bi)*scl;
        }
      }
    __syncthreads();

    char* dh = (region == 0) ? (char*)g_QTH : (char*)g_KTH;
    char* dl = (region == 0) ? (char*)g_QTL : (char*)g_KTL;
    const int nl = tid & 127;
    const int hp = tid >> 7;            // head parity within tile
    const int n = n0 + nl;
    const int head = qc*2 + hp;
    const size_t tb = ((size_t)((b*HEADS + head)*16 + (n>>6)))*16384;
    const uint32_t r6 = n & 63;
    #pragma unroll
    for (int c16 = 0; c16 < 16; c16++){
      float a[8]; __nv_bfloat16 h[8]; float hf[8];
      #pragma unroll
      for (int i=0;i<8;i++) a[i] = T[(hp*128 + c16*8 + i)*132 + nl];
      #pragma unroll
      for (int i=0;i<8;i++){ h[i] = __float2bfloat16(a[i]); hf[i] = __bfloat162float(h[i]); }
      uint4 H, L;
      H.x = pkbf2(hf[0],hf[1]); H.y = pkbf2(hf[2],hf[3]);
      H.z = pkbf2(hf[4],hf[5]); H.w = pkbf2(hf[6],hf[7]);
      L.x = pkbf2(a[0]-hf[0], a[1]-hf[1]);
      L.y = pkbf2(a[2]-hf[2], a[3]-hf[3]);
      L.z = pkbf2(a[4]-hf[4], a[5]-hf[5]);
      L.w = pkbf2(a[6]-hf[6], a[7]-hf[7]);
      uint32_t off = swz256(r6, c16);
      *(uint4*)(dh + tb + off) = H;
      *(uint4*)(dl + tb + off) = L;
    }
  }
}

// ===========================================================================
// Flash attention. S: bf16x3. PV: fp16x2 (P split fp16 hi/lo, V fp16 hi).
// CTA = (b,h) x 128 queries, 256 thr, 8 warps x 16 q-rows.
// ===========================================================================
#define ASTG 49152u
#define AT_SMEM (1024u + 2u*ASTG)

__global__ __launch_bounds__(256, 1) void attn_mma(){
  extern __shared__ char smem[];
  const uint32_t sb = smem_u32(smem);
  const int tid = threadIdx.x;
  const int wid = tid >> 5, lane = tid & 31;
  const int bh = blockIdx.y;
  const int qi = blockIdx.x;           // q block of 128
  const int q0 = qi * 128;
  const int b = bh >> 3, h = bh & 7;

  if (tid == 0){
    MBARRIER_INIT(sb+8, 1); MBARRIER_INIT(sb+16, 1); MBARRIER_INIT(sb+24, 1);
  }
  __syncthreads();

  // ---- Q load: 2 tiles hi + 2 tiles lo = 64KB into stage region
  if (tid == 0){
    MBARRIER_EXPECT_TX(sb+24, 65536);
    const char* qh_g = (const char*)g_QTH + ((size_t)bh*16 + qi*2)*16384;
    const char* ql_g = (const char*)g_QTL + ((size_t)bh*16 + qi*2)*16384;
    BULKCP(sb+1024,         qh_g, 32768, sb+24);
    BULKCP(sb+1024+32768,   ql_g, 32768, sb+24);
  }
  MBARRIER_WAIT_PARITY(sb+24, 0);

  uint32_t qfh[8][4], qfl[8][4];
  {
    uint32_t row = wid*16 + (lane & 15);
    uint32_t base = sb + 1024 + (row >> 6)*16384;
    uint32_t r6 = row & 63;
    #pragma unroll
    for (int kf = 0; kf < 8; kf++){
      uint32_t c16 = kf*2 + (lane >> 4);
      uint32_t addr = base + swz256(r6, c16);
      ldm4(qfh[kf], addr);
      ldm4(qfl[kf], addr + 32768);
    }
  }
  __syncthreads();   // Q consumed; stage region reusable

  const char* kh_g = (const char*)g_KTH + (size_t)bh*16*16384;
  const char* kl_g = (const char*)g_KTL + (size_t)bh*16*16384;
  const char* vh_g = (const char*)g_VH  + (size_t)bh*16*16384;

  auto issueKV = [&](int kb){
    if (tid == 0){
      int buf = kb & 1;
      uint32_t mb = sb + 8 + buf*8;
      MBARRIER_EXPECT_TX(mb, ASTG);
      uint32_t d = sb + 1024 + buf*ASTG;
      BULKCP(d,         kh_g + (size_t)kb*16384, 16384, mb);
      BULKCP(d+16384,   kl_g + (size_t)kb*16384, 16384, mb);
      BULKCP(d+32768,   vh_g + (size_t)kb*16384, 16384, mb);
    }
  };

  float accO[16][4];
  #pragma unroll
  for (int i=0;i<16;i++)
    #pragma unroll
    for (int r=0;r<4;r++) accO[i][r] = 0.f;
  float m0r = -1e30f, m1r = -1e30f, l0 = 0.f, l1 = 0.f;

  issueKV(0);
  for (int kb = 0; kb < 16; kb++){
    if (kb + 1 < 16) issueKV(kb+1);
    MBARRIER_WAIT_PARITY(sb + 8 + (kb&1)*8, (kb>>1)&1);
    const uint32_t st = sb + 1024 + (kb&1)*ASTG;

    // ---- S = Q K^T  (16q x 64k per warp), bf16x3
    float S[8][4];
    #pragma unroll
    for (int i=0;i<8;i++)
      #pragma unroll
      for (int r=0;r<4;r++) S[i][r] = 0.f;
    #pragma unroll
    for (int kf = 0; kf < 8; kf++){
      #pragma unroll
      for (int np = 0; np < 4; np++){
        uint32_t row = np*16 + (lane >> 4)*8 + (lane & 7);
        uint32_t c16 = kf*2 + ((lane >> 3) & 1);
        uint32_t addr = st + swz256(row, c16);
        uint32_t r[4];
        ldm4(r, addr);
        uint32_t b0[2] = {r[0], r[1]}, b1[2] = {r[2], r[3]};
        mma16816(S[np*2],   qfh[kf], b0);
        mma16816(S[np*2+1], qfh[kf], b1);
        mma16816(S[np*2],   qfl[kf], b0);
        mma16816(S[np*2+1], qfl[kf], b1);
        ldm4(r, addr + 16384);
        uint32_t c0[2] = {r[0], r[1]}, c1[2] = {r[2], r[3]};
        mma16816(S[np*2],   qfh[kf], c0);
        mma16816(S[np*2+1], qfh[kf], c1);
      }
    }

    // ---- online softmax (log2 domain; log2e folded into Q)
    float mx0 = -1e30f, mx1 = -1e30f;
    #pragma unroll
    for (int i=0;i<8;i++){
      mx0 = fmaxf(mx0, fmaxf(S[i][0], S[i][1]));
      mx1 = fmaxf(mx1, fmaxf(S[i][2], S[i][3]));
    }
    mx0 = fmaxf(mx0, __shfl_xor_sync(0xffffffffu, mx0, 1));
    mx0 = fmaxf(mx0, __shfl_xor_sync(0xffffffffu, mx0, 2));
    mx1 = fmaxf(mx1, __shfl_xor_sync(0xffffffffu, mx1, 1));
    mx1 = fmaxf(mx1, __shfl_xor_sync(0xffffffffu, mx1, 2));
    float mn0 = fmaxf(m0r, mx0), mn1 = fmaxf(m1r, mx1);
    float al0 = exp2f(m0r - mn0), al1 = exp2f(m1r - mn1);
    m0r = mn0; m1r = mn1;

    float rs0 = 0.f, rs1 = 0.f;
    uint32_t ph[4][4], pl[4][4];
    #pragma unroll
    for (int nf = 0; nf < 8; nf++){
      float p0 = exp2f(S[nf][0] - mn0);
      float p1 = exp2f(S[nf][1] - mn0);
      float p2 = exp2f(S[nf][2] - mn1);
      float p3 = exp2f(S[nf][3] - mn1);
      rs0 += p0 + p1; rs1 += p2 + p3;
      __half h0 = __float2half_rn(p0), h1 = __float2half_rn(p1);
      __half h2 = __float2half_rn(p2), h3 = __float2half_rn(p3);
      int kf = nf >> 1, pc = (nf & 1)*2;
      ph[kf][pc+0] = pkhf2(__half2float(h0), __half2float(h1));
      ph[kf][pc+1] = pkhf2(__half2float(h2), __half2float(h3));
      pl[kf][pc+0] = pkhf2(p0-__half2float(h0), p1-__half2float(h1));
      pl[kf][pc+1] = pkhf2(p2-__half2float(h2), p3-__half2float(h3));
    }
    rs0 += __shfl_xor_sync(0xffffffffu, rs0, 1);
    rs0 += __shfl_xor_sync(0xffffffffu, rs0, 2);
    rs1 += __shfl_xor_sync(0xffffffffu, rs1, 1);
    rs1 += __shfl_xor_sync(0xffffffffu, rs1, 2);
    l0 = l0*al0 + rs0; l1 = l1*al1 + rs1;

    #pragma unroll
    for (int i=0;i<16;i++){
      accO[i][0] *= al0; accO[i][1] *= al0;
      accO[i][2] *= al1; accO[i][3] *= al1;
    }

    // ---- accO += P V  (16q x 128d per warp), fp16x2 (V hi only)
    const uint32_t vb = st + 32768;
    #pragma unroll
    for (int kf = 0; kf < 4; kf++){
      #pragma unroll
      for (int np = 0; np < 8; np++){
        uint32_t row = np*16 + (lane >> 4)*8 + (lane & 7);
        uint32_t c16 = kf*2 + ((lane >> 3) & 1);
        uint32_t addr = vb + swz128(row, c16);
        uint32_t r[4];
        ldm4(r, addr);
        uint32_t b0[2] = {r[0], r[1]}, b1[2] = {r[2], r[3]};
        mma16816h(accO[np*2],   ph[kf], b0);
        mma16816h(accO[np*2+1], ph[kf], b1);
        mma16816h(accO[np*2],   pl[kf], b0);
        mma16816h(accO[np*2+1], pl[kf], b1);
      }
    }
    __syncthreads();
  }

  // ---- epilogue: O/l -> fp16 hi/lo into tiled OT
  float inv0 = 1.f / l0, inv1 = 1.f / l1;
  int na = q0 + wid*16 + (lane >> 2);
  int nb2 = na + 8;
  #pragma unroll
  for (int nf = 0; nf < 16; nf++){
    int ch = h*HD + nf*8 + (lane & 3)*2;
    float v0 = accO[nf][0]*inv0, v1 = accO[nf][1]*inv0;
    float v2 = accO[nf][2]*inv1, v3 = accO[nf][3]*inv1;
    __half h0 = __float2half_rn(v0), h1 = __float2half_rn(v1);
    __half h2 = __float2half_rn(v2), h3 = __float2half_rn(v3);
    size_t tba = ((size_t)((b*8 + (na>>7))*32 + (ch>>5)))*8192;
    size_t tbb = ((size_t)((b*8 + (nb2>>7))*32 + (ch>>5)))*8192;
    uint32_t ofa = swz64(na & 127, (ch>>3)&3) + (ch&7)*2;
    uint32_t ofb = swz64(nb2 & 127, (ch>>3)&3) + (ch&7)*2;
    *(uint32_t*)((char*)g_OTH + tba + ofa) = pkhf2(__half2float(h0), __half2float(h1));
    *(uint32_t*)((char*)g_OTL + tba + ofa) = pkhf2(v0-__half2float(h0), v1-__half2float(h1));
    *(uint32_t*)((char*)g_OTH + tbb + ofb) = pkhf2(__half2float(h2), __half2float(h3));
    *(uint32_t*)((char*)g_OTL + tbb + ofb) = pkhf2(v2-__half2float(h2), v3-__half2float(h3));
  }
}

// ---------------------------------------------------------------------------
// Quaternion depthwise 3x3. WRITES (=) conv + pe-bias to output; proj GEMM
// accumulates on top. Runs on a side stream concurrent with GEMM1/attention.
// ---------------------------------------------------------------------------
__global__ __launch_bounds__(256) void qdwconv_kernel(const float* __restrict__ x,
                                                      const float* __restrict__ w_pe,
                                                      const float* __restrict__ b_pe,
                                                      float* __restrict__ outp){
  __shared__ float xs[4][1024];
  __shared__ float wt[4][4][9];
  const int bid = blockIdx.x;
  const int c = bid & 255, b = bid >> 8;
  const int tid = threadIdx.x;

  #pragma unroll
  for (int p=0;p<4;p++){
    const float* xp = x + ((size_t)((b*CC + c)*4 + p))*NPIX;
    for (int k=tid; k<1024; k+=256) xs[p][k] = xp[k];
  }
  if (tid < 144){
    int qc = tid/36, p = (tid/9)&3, t = tid%9;
    wt[qc][p][t] = c_SGN[qc*4+p] * w_pe[(c_IDX[qc*4+p]*CC + c)*9 + t];
  }
  __syncthreads();

  float bia[4];
  #pragma unroll
  for (int qc=0;qc<4;qc++) bia[qc] = b_pe[qc*CC + c];

  for (int k=tid; k<1024; k+=256){
    int hh = k >> 5, ww = k & 31;
    float acc[4] = {bia[0],bia[1],bia[2],bia[3]};
    #pragma unroll
    for (int p=0;p<4;p++){
      #pragma unroll
      for (int kh=0;kh<3;kh++){
        int h2 = hh + kh - 1;
        if (h2 < 0 || h2 > 31) continue;
        #pragma unroll
        for (int kw=0;kw<3;kw++){
          int w2 = ww + kw - 1;
          if (w2 < 0 || w2 > 31) continue;
          float xv = xs[p][h2*32 + w2];
          #pragma unroll
          for (int qc=0;qc<4;qc++) acc[qc] = fmaf(wt[qc][p][kh*3+kw], xv, acc[qc]);
        }
      }
    }
    #pragma unroll
    for (int qc=0;qc<4;qc++)
      outp[((size_t)((b*CC + c)*4 + qc))*NPIX + k] = acc[qc];
  }
}

// ---------------------------------------------------------------------------
extern "C" void kernel_launch(void* const* d_in, const int* in_sizes, int n_in,
                              void* d_out, int out_size){
  const float* x      = (const float*)d_in[0];
  const float* w_qkv  = (const float*)d_in[1];
  const float* b_qkv  = (const float*)d_in[2];
  const float* w_proj = (const float*)d_in[3];
  const float* b_proj = (const float*)d_in[4];
  const float* w_pe   = (const float*)d_in[5];
  const float* b_pe   = (const float*)d_in[6];
  float* outp = (float*)d_out;

  (void)in_sizes; (void)n_in; (void)out_size;

  static cudaStream_t s2 = nullptr;
  static cudaEvent_t eFork = nullptr, eJoin = nullptr;
  if (s2 == nullptr){
    cudaStreamCreateWithFlags(&s2, cudaStreamNonBlocking);
    cudaEventCreateWithFlags(&eFork, cudaEventDisableTiming);
    cudaEventCreateWithFlags(&eJoin, cudaEventDisableTiming);
  }

  cudaFuncSetAttribute(gemm_mma<0>, cudaFuncAttributeMaxDynamicSharedMemorySize,
                       GEMM_SMEM0);
  cudaFuncSetAttribute(gemm_mma<1>, cudaFuncAttributeMaxDynamicSharedMemorySize,
                       GEMM_SMEM1);
  cudaFuncSetAttribute(attn_mma, cudaFuncAttributeMaxDynamicSharedMemorySize,
                       AT_SMEM);

  // ---- fork: dwconv runs on side stream, concurrent with the main chain ----
  cudaEventRecord(eFork, 0);
  cudaStreamWaitEvent(s2, eFork, 0);
  qdwconv_kernel<<< NB*CC, 256, 0, s2 >>>(x, w_pe, b_pe, outp);
  cudaEventRecord(eJoin, s2);

  // ---- main chain ----
  void *weffH, *weffL, *wprojH;
  cudaGetSymbolAddress(&weffH, g_WeffH);
  cudaGetSymbolAddress(&weffL, g_WeffL);
  cudaGetSymbolAddress(&wprojH, g_WprojH);
  prep_w_kernel<<< MQKV*128/256, 256 >>>(w_qkv, (char*)weffH, (char*)weffL, 1);
  prep_w_kernel<<< DIM*128/256, 256 >>>(w_proj, (char*)wprojH, nullptr, 0);
  prep_xt_kernel<<< dim3(32,32,8), 256 >>>(x);

  // QKV GEMM: emits Q/K bf16 (n,d) and V fp16 (d,n) tiles directly
  gemm_mma<0><<< dim3(12,64), 256, GEMM_SMEM0 >>>(b_qkv, nullptr);

  // Attention: mma.sync flash, 8 q-tiles x 64 (b,h)
  attn_mma<<< dim3(8,64), 256, AT_SMEM >>>();

  // ---- join: dwconv output must be in place before proj accumulates ----
  cudaStreamWaitEvent(0, eJoin, 0);

  // Proj: (1024 x 8192) fp16x2 -> accumulate into final output
  gemm_mma<1><<< dim3(4,64), 256, GEMM_SMEM1 >>>(b_proj, outp);
}

// round 11
// speedup vs baseline: 1.4067x; 1.2208x over previous
#include <cuda_runtime.h>
#include <cuda_bf16.h>
#include <cuda_fp16.h>
#include <cstdint>
#include <math.h>

#define NB 8
#define CC 256
#define NPIX 1024
#define HEADS 8
#define HD 128
#define MQKV 3072
#define DIM 1024

// Hamilton tables
__constant__ int   c_IDX[16] = {0,1,2,3, 1,0,3,2, 2,3,0,1, 3,2,1,0};
__constant__ float c_SGN[16] = {1.f,-1.f,-1.f,-1.f, 1.f,1.f,1.f,-1.f,
                                1.f,-1.f,1.f,1.f, 1.f,1.f,-1.f,1.f};

// Scratch (device globals). ALL tensor-core operands pre-tiled + pre-swizzled
// (fp16), fetched with single cp.async.bulk copies.
__device__ __half g_WeffH[(size_t)MQKV*DIM];        // fp16 hi only
__device__ __half g_WprojH[(size_t)DIM*DIM];        // fp16 hi only
__device__ __half g_XTH[(size_t)NB*NPIX*DIM];       // fp16 hi
__device__ __half g_XTL[(size_t)NB*NPIX*DIM];       // fp16 lo (exact residual)
__device__ __half g_OTH[(size_t)NB*NPIX*DIM];       // fp16 hi
__device__ __half g_OTL[(size_t)NB*NPIX*DIM];       // fp16 lo
__device__ __half g_QTH[(size_t)NB*HEADS*NPIX*HD];  // fp16 hi (scale folded)
__device__ __half g_QTL[(size_t)NB*HEADS*NPIX*HD];  // fp16 lo
__device__ __half g_KTH[(size_t)NB*HEADS*NPIX*HD];  // fp16 hi only
__device__ __half g_VH[(size_t)NB*HEADS*HD*NPIX];   // fp16 hi only

// ===========================================================================
// Helpers
// ===========================================================================
__device__ __forceinline__ uint32_t smem_u32(const void* p){
  uint32_t a;
  asm("{ .reg .u64 t; cvta.to.shared.u64 t, %1; cvt.u32.u64 %0, t; }"
      : "=r"(a) : "l"(p));
  return a;
}
__device__ __forceinline__ void ldm4(uint32_t r[4], uint32_t addr){
  asm volatile("ldmatrix.sync.aligned.m8n8.x4.shared.b16 {%0,%1,%2,%3}, [%4];"
    : "=r"(r[0]),"=r"(r[1]),"=r"(r[2]),"=r"(r[3]) : "r"(addr));
}
__device__ __forceinline__ void mma16816h(float c[4], const uint32_t a[4],
                                          const uint32_t b[2]){
  asm volatile(
    "mma.sync.aligned.m16n8k16.row.col.f32.f16.f16.f32 "
    "{%0,%1,%2,%3}, {%4,%5,%6,%7}, {%8,%9}, {%0,%1,%2,%3};"
    : "+f"(c[0]),"+f"(c[1]),"+f"(c[2]),"+f"(c[3])
    : "r"(a[0]),"r"(a[1]),"r"(a[2]),"r"(a[3]), "r"(b[0]),"r"(b[1]));
}
__device__ __forceinline__ uint32_t pkhf2(float a, float b){
  __half2 t = __floats2half2_rn(a, b);
  return *(uint32_t*)&t;
}
#define BULKCP(dst, src, bytes, mb) \
  asm volatile("cp.async.bulk.shared::cluster.global.mbarrier::complete_tx::bytes [%0], [%1], %2, [%3];" \
    :: "r"((uint32_t)(dst)), "l"(src), "r"((uint32_t)(bytes)), "r"((uint32_t)(mb)) : "memory")
#define MBARRIER_INIT(mb, c) \
  asm volatile("mbarrier.init.shared.b64 [%0], %1;" :: "r"((uint32_t)(mb)), "r"((uint32_t)(c)) : "memory")
#define MBARRIER_EXPECT_TX(mb, tx) \
  asm volatile("mbarrier.arrive.expect_tx.shared.b64 _, [%0], %1;" :: "r"((uint32_t)(mb)), "r"((uint32_t)(tx)) : "memory")
#define MBARRIER_WAIT_PARITY(mb, ph) do { \
    uint32_t _m = (uint32_t)(mb); uint32_t _p = (uint32_t)(ph); uint32_t _d; \
    asm volatile("{\n\t.reg .pred p;\n\t" \
        "mbarrier.try_wait.parity.acquire.cta.shared::cta.b64 p, [%1], %2;\n\t" \
        "selp.b32 %0, 1, 0, p;\n\t}" : "=r"(_d) : "r"(_m), "r"(_p) : "memory"); \
    if (!_d) { \
      asm volatile("{\n\t.reg .pred P1;\n\t" \
        "WL_%=:\n\t" \
        "mbarrier.try_wait.parity.acquire.cta.shared::cta.b64 P1, [%0], %1, 0x989680;\n\t" \
        "@P1 bra.uni WD_%=;\n\t" \
        "bra.uni WL_%=;\n\t" \
        "WD_%=:\n\t}" :: "r"(_m), "r"(_p) : "memory"); \
    } \
  } while(0)

// swizzled byte offsets inside tiles (row-major rows of 64/128/256 bytes)
__device__ __forceinline__ uint32_t swz64 (uint32_t r, uint32_t c16){ return r*64u  + ((c16 ^ ((r>>1)&3u))<<4); }
__device__ __forceinline__ uint32_t swz128(uint32_t r, uint32_t c16){ return r*128u + ((c16 ^ (r&7u))<<4); }
__device__ __forceinline__ uint32_t swz256(uint32_t r, uint32_t c16){ return r*256u + ((c16 ^ (r&7u))<<4); }

// ===========================================================================
// Prep: Hamilton-folded weights -> fp16 hi only, tiled+swizzled
// ===========================================================================
__global__ void prep_w_kernel(const float* __restrict__ w,
                              char* __restrict__ outH, int is_qkv){
  int idx = blockIdx.x*256 + threadIdx.x;     // chunk id: M*128
  int g = idx >> 7, c = idx & 127;
  int k0 = c*8;
  int qc, o;
  if (is_qkv){ qc = g / 768; o = g - qc*768; } else { qc = g >> 8; o = g & 255; }
  int p = k0 >> 8, cch = k0 & 255;
  float s = c_SGN[qc*4+p];
  const float* src = w + ((size_t)(c_IDX[qc*4+p]*(is_qkv?768:256) + o))*256 + cch;
  float4 v0 = *(const float4*)src;
  float4 v1 = *(const float4*)(src+4);
  float a[8] = {v0.x*s,v0.y*s,v0.z*s,v0.w*s, v1.x*s,v1.y*s,v1.z*s,v1.w*s};
  size_t base = ((size_t)((g>>8)*32 + (c>>2)))*16384;
  uint32_t off = swz64(g & 255, c & 3);
  uint4 H;
  H.x = pkhf2(a[0],a[1]); H.y = pkhf2(a[2],a[3]);
  H.z = pkhf2(a[4],a[5]); H.w = pkhf2(a[6],a[7]);
  *(uint4*)(outH + base + off) = H;
}

// x (b, cch, p, n) fp32 -> XT tiles (b, ntile, kt) fp16 hi/lo (exact split)
__global__ void prep_xt_kernel(const float* __restrict__ x){
  __shared__ float sm[32][33];
  int b = blockIdx.z, k0 = blockIdx.x*32, n0 = blockIdx.y*32;
  int t = threadIdx.x;
  {
    int kk = t >> 3, n4 = (t & 7) << 2;
    int k = k0 + kk; int p = k >> 8, cch = k & 255;
    float4 v = *(const float4*)&x[((size_t)((b*CC+cch)*4 + p))*NPIX + n0 + n4];
    sm[kk][n4] = v.x; sm[kk][n4+1] = v.y; sm[kk][n4+2] = v.z; sm[kk][n4+3] = v.w;
  }
  __syncthreads();
  {
    int nn = t >> 3, k4 = (t & 7) << 2;
    int n = n0 + nn;
    float a[4]; __half hh[4]; float hf[4];
    #pragma unroll
    for (int i=0;i<4;i++){ a[i] = sm[k4+i][nn]; hh[i] = __float2half_rn(a[i]); hf[i] = __half2float(hh[i]); }
    uint2 hp = make_uint2(pkhf2(hf[0],hf[1]), pkhf2(hf[2],hf[3]));
    uint2 lp = make_uint2(pkhf2(a[0]-hf[0], a[1]-hf[1]),
                          pkhf2(a[2]-hf[2], a[3]-hf[3]));
    size_t tb = ((size_t)((b*8 + (n>>7))*32 + (k0>>5)))*8192;
    uint32_t off = swz64(n & 127, k4 >> 3) + ((k4 >> 2) & 1)*8;
    *(uint2*)((char*)g_XTH + tb + off) = hp;
    *(uint2*)((char*)g_XTL + tb + off) = lp;
  }
}

// ===========================================================================
// Unified fp16x2 GEMM: 256m x 128n per CTA, K=1024, BK=64 bulk-fed.
// A fp16 hi-only; B fp16 hi+lo: D = Ah*(Bh+Bl). 2 mma passes.
// MODE 0: A=Weff, B=XT. Fused epilogue -> Q hi/lo, K hi, V hi fp16 tiles.
// MODE 1: A=Wproj, B=OT. Accumulates into final out (+bias).
// ===========================================================================
#define GSTG 65536u
#define GEMM_SMEM 136192u   // max(1024 + 2*GSTG, 1024 + 256*132*4 epilogue T)

template<int MODE>
__global__ __launch_bounds__(256, 1) void gemm_mma(const float* __restrict__ bias,
                                                   float* __restrict__ outp){
  extern __shared__ char smem[];
  const uint32_t sb = smem_u32(smem);
  const int tid = threadIdx.x;
  const int wid = tid >> 5, lane = tid & 31;
  const int mt = blockIdx.x;
  const int b  = blockIdx.y >> 3;
  const int nt = blockIdx.y & 7;
  const int m0 = mt*256, n0 = nt*128;
  const int wm = (wid >> 1) * 64;
  const int wn = (wid & 1) * 64;

  const char* Ahb = (const char*)(MODE==0 ? (void*)g_WeffH : (void*)g_WprojH) + (size_t)mt*32*16384;
  const char* Bhb = (const char*)(MODE==0 ? (void*)g_XTH : (void*)g_OTH) + (size_t)((b*8+nt)*32)*8192;
  const char* Blb = (const char*)(MODE==0 ? (void*)g_XTL : (void*)g_OTL) + (size_t)((b*8+nt)*32)*8192;

  if (tid == 0){ MBARRIER_INIT(sb+8, 1); MBARRIER_INIT(sb+16, 1); }
  __syncthreads();

  float acc[4][8][4];
  #pragma unroll
  for (int i=0;i<4;i++)
    #pragma unroll
    for (int j=0;j<8;j++)
      #pragma unroll
      for (int r=0;r<4;r++) acc[i][j][r] = 0.f;

  auto issue = [&](int kt2){
    if (tid == 0){
      int buf = kt2 & 1;
      uint32_t mb = sb + 8 + buf*8;
      MBARRIER_EXPECT_TX(mb, GSTG);
      uint32_t d = sb + 1024 + buf*GSTG;
      BULKCP(d,         Ahb + (size_t)kt2*32768, 32768, mb);
      BULKCP(d+32768,   Bhb + (size_t)kt2*16384, 16384, mb);
      BULKCP(d+49152,   Blb + (size_t)kt2*16384, 16384, mb);
    }
  };

  issue(0);
  for (int kt2 = 0; kt2 < 16; kt2++){
    if (kt2 + 1 < 16) issue(kt2+1);
    MBARRIER_WAIT_PARITY(sb + 8 + (kt2&1)*8, (kt2>>1)&1);
    const uint32_t st = sb + 1024 + (kt2&1)*GSTG;

    #pragma unroll
    for (int s = 0; s < 2; s++){
      const uint32_t Ah = st + s*16384;
      const uint32_t Bh = st + 32768 + s*8192;
      #pragma unroll
      for (int ks = 0; ks < 2; ks++){
        uint32_t ah[4][4], bh[8][2], bl[8][2];
        #pragma unroll
        for (int mi = 0; mi < 4; mi++){
          uint32_t row = wm + mi*16 + (lane & 15);
          uint32_t c16 = ks*2 + (lane >> 4);
          ldm4(ah[mi], Ah + swz64(row, c16));
        }
        #pragma unroll
        for (int np = 0; np < 4; np++){
          uint32_t row = wn + np*16 + (lane >> 4)*8 + (lane & 7);
          uint32_t c16 = ks*2 + ((lane >> 3) & 1);
          uint32_t addr = Bh + swz64(row, c16);
          uint32_t r[4];
          ldm4(r, addr);
          bh[np*2][0]=r[0]; bh[np*2][1]=r[1]; bh[np*2+1][0]=r[2]; bh[np*2+1][1]=r[3];
          ldm4(r, addr + 16384);          // Bl tile = Bh + 16384 (same s)
          bl[np*2][0]=r[0]; bl[np*2][1]=r[1]; bl[np*2+1][0]=r[2]; bl[np*2+1][1]=r[3];
        }
        #pragma unroll
        for (int mi=0;mi<4;mi++)
          #pragma unroll
          for (int ni=0;ni<8;ni++) mma16816h(acc[mi][ni], ah[mi], bh[ni]);
        #pragma unroll
        for (int mi=0;mi<4;mi++)
          #pragma unroll
          for (int ni=0;ni<8;ni++) mma16816h(acc[mi][ni], ah[mi], bl[ni]);
      }
    }
    __syncthreads();
  }

  if (MODE == 1){
    // final output: out[(b, cch, qc, n)] += acc + bias  (dwconv pre-wrote)
    #pragma unroll
    for (int mi=0;mi<4;mi++)
      #pragma unroll
      for (int half=0; half<2; half++){
        int gm = m0 + wm + mi*16 + (lane >> 2) + half*8;
        float bi = bias[gm];
        int qc = gm >> 8; int cch = gm & 255;
        float* dst = outp + ((size_t)((b*CC + cch)*4 + qc))*NPIX;
        #pragma unroll
        for (int ni=0;ni<8;ni++){
          int nn = n0 + wn + ni*8 + (lane & 3)*2;
          float2 old = *(float2*)&dst[nn];
          float2 v = make_float2(old.x + acc[mi][ni][half*2+0] + bi,
                                 old.y + acc[mi][ni][half*2+1] + bi);
          *(float2*)&dst[nn] = v;
        }
      }
    return;
  }

  // ---- MODE 0 epilogue: region = Q(0) / K(1) / V(2) ----
  const int region = mt % 3;
  const int qc = mt / 3;
  if (region == 2){
    // V: fp16 hi-only stores into (d, n) tiles
    #pragma unroll
    for (int mi=0;mi<4;mi++)
      #pragma unroll
      for (int half=0; half<2; half++){
        int gm = m0 + wm + mi*16 + (lane >> 2) + half*8;
        float bi = bias[gm];
        int o = gm - qc*768; int cch = o & 255;
        int ch = (qc << 8) | cch; int hh = ch >> 7; int dd = ch & 127;
        size_t bhbase = ((size_t)(b*HEADS + hh))*16*16384;
        #pragma unroll
        for (int ni=0;ni<8;ni++){
          int nn = n0 + wn + ni*8 + (lane & 3)*2;
          float v0 = acc[mi][ni][half*2+0] + bi;
          float v1 = acc[mi][ni][half*2+1] + bi;
          size_t tb = bhbase + (size_t)(nn>>6)*16384;
          uint32_t off = swz128(dd, (nn&63)>>3) + (nn&7)*2;
          *(uint32_t*)((char*)g_VH + tb + off) = pkhf2(v0, v1);
        }
      }
  } else {
    // Q/K: stage fp32 into smem (scale folded), transpose, emit (n,d) tiles.
    // Q: fp16 hi + lo (exact split). K: fp16 hi only.
    float* T = (float*)(smem + 1024);   // 256 x 132 fp32 = 135168 B
    const float scl = (region == 0) ? 0.12751875542484462f  // qscale*log2e
                                    : 1.f;
    #pragma unroll
    for (int mi=0;mi<4;mi++)
      #pragma unroll
      for (int half=0; half<2; half++){
        int gm = m0 + wm + mi*16 + (lane >> 2) + half*8;
        int row = gm - m0;
        float bi = bias[gm];
        #pragma unroll
        for (int ni=0;ni<8;ni++){
          int nn = wn + ni*8 + (lane & 3)*2;
          T[row*132 + nn]     = (acc[mi][ni][half*2+0] + bi)*scl;
          T[row*132 + nn + 1] = (acc[mi][ni][half*2+1] + bi)*scl;
        }
      }
    __syncthreads();

    char* dh = (region == 0) ? (char*)g_QTH : (char*)g_KTH;
    char* dl = (char*)g_QTL;            // used only for region 0
    const int nl = tid & 127;
    const int hp = tid >> 7;            // head parity within tile
    const int n = n0 + nl;
    const int head = qc*2 + hp;
    const size_t tb = ((size_t)((b*HEADS + head)*16 + (n>>6)))*16384;
    const uint32_t r6 = n & 63;
    #pragma unroll
    for (int c16 = 0; c16 < 16; c16++){
      float a[8]; __half h[8]; float hf[8];
      #pragma unroll
      for (int i=0;i<8;i++) a[i] = T[(hp*128 + c16*8 + i)*132 + nl];
      #pragma unroll
      for (int i=0;i<8;i++){ h[i] = __float2half_rn(a[i]); hf[i] = __half2float(h[i]); }
      uint4 H;
      H.x = pkhf2(hf[0],hf[1]); H.y = pkhf2(hf[2],hf[3]);
      H.z = pkhf2(hf[4],hf[5]); H.w = pkhf2(hf[6],hf[7]);
      uint32_t off = swz256(r6, c16);
      *(uint4*)(dh + tb + off) = H;
      if (region == 0){
        uint4 L;
        L.x = pkhf2(a[0]-hf[0], a[1]-hf[1]);
        L.y = pkhf2(a[2]-hf[2], a[3]-hf[3]);
        L.z = pkhf2(a[4]-hf[4], a[5]-hf[5]);
        L.w = pkhf2(a[6]-hf[6], a[7]-hf[7]);
        *(uint4*)(dl + tb + off) = L;
      }
    }
  }
}

// ===========================================================================
// Flash attention, all fp16x2. S = (Qh+Ql)*Kh; PV = (Ph+Pl)*Vh.
// CTA = (b,h) x 128 queries, 256 thr, 8 warps x 16 q-rows.
// ===========================================================================
#define ASTG 32768u
#define AT_SMEM (1024u + 2u*ASTG)

__global__ __launch_bounds__(256, 1) void attn_mma(){
  extern __shared__ char smem[];
  const uint32_t sb = smem_u32(smem);
  const int tid = threadIdx.x;
  const int wid = tid >> 5, lane = tid & 31;
  const int bh = blockIdx.y;
  const int qi = blockIdx.x;           // q block of 128
  const int q0 = qi * 128;
  const int b = bh >> 3, h = bh & 7;

  if (tid == 0){
    MBARRIER_INIT(sb+8, 1); MBARRIER_INIT(sb+16, 1); MBARRIER_INIT(sb+24, 1);
  }
  __syncthreads();

  // ---- Q load: 2 tiles hi + 2 tiles lo = 64KB into the stage region
  if (tid == 0){
    MBARRIER_EXPECT_TX(sb+24, 65536);
    const char* qh_g = (const char*)g_QTH + ((size_t)bh*16 + qi*2)*16384;
    const char* ql_g = (const char*)g_QTL + ((size_t)bh*16 + qi*2)*16384;
    BULKCP(sb+1024,         qh_g, 32768, sb+24);
    BULKCP(sb+1024+32768,   ql_g, 32768, sb+24);
  }
  MBARRIER_WAIT_PARITY(sb+24, 0);

  uint32_t qfh[8][4], qfl[8][4];
  {
    uint32_t row = wid*16 + (lane & 15);
    uint32_t base = sb + 1024 + (row >> 6)*16384;
    uint32_t r6 = row & 63;
    #pragma unroll
    for (int kf = 0; kf < 8; kf++){
      uint32_t c16 = kf*2 + (lane >> 4);
      uint32_t addr = base + swz256(r6, c16);
      ldm4(qfh[kf], addr);
      ldm4(qfl[kf], addr + 32768);
    }
  }
  __syncthreads();   // Q consumed; stage region reusable

  const char* kh_g = (const char*)g_KTH + (size_t)bh*16*16384;
  const char* vh_g = (const char*)g_VH  + (size_t)bh*16*16384;

  auto issueKV = [&](int kb){
    if (tid == 0){
      int buf = kb & 1;
      uint32_t mb = sb + 8 + buf*8;
      MBARRIER_EXPECT_TX(mb, ASTG);
      uint32_t d = sb + 1024 + buf*ASTG;
      BULKCP(d,         kh_g + (size_t)kb*16384, 16384, mb);
      BULKCP(d+16384,   vh_g + (size_t)kb*16384, 16384, mb);
    }
  };

  float accO[16][4];
  #pragma unroll
  for (int i=0;i<16;i++)
    #pragma unroll
    for (int r=0;r<4;r++) accO[i][r] = 0.f;
  float m0r = -1e30f, m1r = -1e30f, l0 = 0.f, l1 = 0.f;

  issueKV(0);
  for (int kb = 0; kb < 16; kb++){
    if (kb + 1 < 16) issueKV(kb+1);
    MBARRIER_WAIT_PARITY(sb + 8 + (kb&1)*8, (kb>>1)&1);
    const uint32_t st = sb + 1024 + (kb&1)*ASTG;

    // ---- S = (Qh+Ql) Kh^T  (16q x 64k per warp), fp16x2
    float S[8][4];
    #pragma unroll
    for (int i=0;i<8;i++)
      #pragma unroll
      for (int r=0;r<4;r++) S[i][r] = 0.f;
    #pragma unroll
    for (int kf = 0; kf < 8; kf++){
      #pragma unroll
      for (int np = 0; np < 4; np++){
        uint32_t row = np*16 + (lane >> 4)*8 + (lane & 7);
        uint32_t c16 = kf*2 + ((lane >> 3) & 1);
        uint32_t r[4];
        ldm4(r, st + swz256(row, c16));
        uint32_t b0[2] = {r[0], r[1]}, b1[2] = {r[2], r[3]};
        mma16816h(S[np*2],   qfh[kf], b0);
        mma16816h(S[np*2+1], qfh[kf], b1);
        mma16816h(S[np*2],   qfl[kf], b0);
        mma16816h(S[np*2+1], qfl[kf], b1);
      }
    }

    // ---- online softmax (log2 domain; log2e folded into Q)
    float mx0 = -1e30f, mx1 = -1e30f;
    #pragma unroll
    for (int i=0;i<8;i++){
      mx0 = fmaxf(mx0, fmaxf(S[i][0], S[i][1]));
      mx1 = fmaxf(mx1, fmaxf(S[i][2], S[i][3]));
    }
    mx0 = fmaxf(mx0, __shfl_xor_sync(0xffffffffu, mx0, 1));
    mx0 = fmaxf(mx0, __shfl_xor_sync(0xffffffffu, mx0, 2));
    mx1 = fmaxf(mx1, __shfl_xor_sync(0xffffffffu, mx1, 1));
    mx1 = fmaxf(mx1, __shfl_xor_sync(0xffffffffu, mx1, 2));
    float mn0 = fmaxf(m0r, mx0), mn1 = fmaxf(m1r, mx1);
    float al0 = exp2f(m0r - mn0), al1 = exp2f(m1r - mn1);
    m0r = mn0; m1r = mn1;

    float rs0 = 0.f, rs1 = 0.f;
    uint32_t ph[4][4], pl[4][4];
    #pragma unroll
    for (int nf = 0; nf < 8; nf++){
      float p0 = exp2f(S[nf][0] - mn0);
      float p1 = exp2f(S[nf][1] - mn0);
      float p2 = exp2f(S[nf][2] - mn1);
      float p3 = exp2f(S[nf][3] - mn1);
      rs0 += p0 + p1; rs1 += p2 + p3;
      __half h0 = __float2half_rn(p0), h1 = __float2half_rn(p1);
      __half h2 = __float2half_rn(p2), h3 = __float2half_rn(p3);
      int kf = nf >> 1, pc = (nf & 1)*2;
      ph[kf][pc+0] = pkhf2(__half2float(h0), __half2float(h1));
      ph[kf][pc+1] = pkhf2(__half2float(h2), __half2float(h3));
      pl[kf][pc+0] = pkhf2(p0-__half2float(h0), p1-__half2float(h1));
      pl[kf][pc+1] = pkhf2(p2-__half2float(h2), p3-__half2float(h3));
    }
    rs0 += __shfl_xor_sync(0xffffffffu, rs0, 1);
    rs0 += __shfl_xor_sync(0xffffffffu, rs0, 2);
    rs1 += __shfl_xor_sync(0xffffffffu, rs1, 1);
    rs1 += __shfl_xor_sync(0xffffffffu, rs1, 2);
    l0 = l0*al0 + rs0; l1 = l1*al1 + rs1;

    #pragma unroll
    for (int i=0;i<16;i++){
      accO[i][0] *= al0; accO[i][1] *= al0;
      accO[i][2] *= al1; accO[i][3] *= al1;
    }

    // ---- accO += (Ph+Pl) Vh  (16q x 128d per warp), fp16x2
    const uint32_t vb = st + 16384;
    #pragma unroll
    for (int kf = 0; kf < 4; kf++){
      #pragma unroll
      for (int np = 0; np < 8; np++){
        uint32_t row = np*16 + (lane >> 4)*8 + (lane & 7);
        uint32_t c16 = kf*2 + ((lane >> 3) & 1);
        uint32_t r[4];
        ldm4(r, vb + swz128(row, c16));
        uint32_t b0[2] = {r[0], r[1]}, b1[2] = {r[2], r[3]};
        mma16816h(accO[np*2],   ph[kf], b0);
        mma16816h(accO[np*2+1], ph[kf], b1);
        mma16816h(accO[np*2],   pl[kf], b0);
        mma16816h(accO[np*2+1], pl[kf], b1);
      }
    }
    __syncthreads();
  }

  // ---- epilogue: O/l -> fp16 hi/lo into tiled OT
  float inv0 = 1.f / l0, inv1 = 1.f / l1;
  int na = q0 + wid*16 + (lane >> 2);
  int nb2 = na + 8;
  #pragma unroll
  for (int nf = 0; nf < 16; nf++){
    int ch = h*HD + nf*8 + (lane & 3)*2;
    float v0 = accO[nf][0]*inv0, v1 = accO[nf][1]*inv0;
    float v2 = accO[nf][2]*inv1, v3 = accO[nf][3]*inv1;
    __half h0 = __float2half_rn(v0), h1 = __float2half_rn(v1);
    __half h2 = __float2half_rn(v2), h3 = __float2half_rn(v3);
    size_t tba = ((size_t)((b*8 + (na>>7))*32 + (ch>>5)))*8192;
    size_t tbb = ((size_t)((b*8 + (nb2>>7))*32 + (ch>>5)))*8192;
    uint32_t ofa = swz64(na & 127, (ch>>3)&3) + (ch&7)*2;
    uint32_t ofb = swz64(nb2 & 127, (ch>>3)&3) + (ch&7)*2;
    *(uint32_t*)((char*)g_OTH + tba + ofa) = pkhf2(__half2float(h0), __half2float(h1));
    *(uint32_t*)((char*)g_OTL + tba + ofa) = pkhf2(v0-__half2float(h0), v1-__half2float(h1));
    *(uint32_t*)((char*)g_OTH + tbb + ofb) = pkhf2(__half2float(h2), __half2float(h3));
    *(uint32_t*)((char*)g_OTL + tbb + ofb) = pkhf2(v2-__half2float(h2), v3-__half2float(h3));
  }
}

// ---------------------------------------------------------------------------
// Quaternion depthwise 3x3. WRITES (=) conv + pe-bias to output; proj GEMM
// accumulates on top. Runs on a side stream concurrent with the main chain.
// ---------------------------------------------------------------------------
__global__ __launch_bounds__(256) void qdwconv_kernel(const float* __restrict__ x,
                                                      const float* __restrict__ w_pe,
                                                      const float* __restrict__ b_pe,
                                                      float* __restrict__ outp){
  __shared__ float xs[4][1024];
  __shared__ float wt[4][4][9];
  const int bid = blockIdx.x;
  const int c = bid & 255, b = bid >> 8;
  const int tid = threadIdx.x;

  #pragma unroll
  for (int p=0;p<4;p++){
    const float* xp = x + ((size_t)((b*CC + c)*4 + p))*NPIX;
    for (int k=tid; k<1024; k+=256) xs[p][k] = xp[k];
  }
  if (tid < 144){
    int qc = tid/36, p = (tid/9)&3, t = tid%9;
    wt[qc][p][t] = c_SGN[qc*4+p] * w_pe[(c_IDX[qc*4+p]*CC + c)*9 + t];
  }
  __syncthreads();

  float bia[4];
  #pragma unroll
  for (int qc=0;qc<4;qc++) bia[qc] = b_pe[qc*CC + c];

  for (int k=tid; k<1024; k+=256){
    int hh = k >> 5, ww = k & 31;
    float acc[4] = {bia[0],bia[1],bia[2],bia[3]};
    #pragma unroll
    for (int p=0;p<4;p++){
      #pragma unroll
      for (int kh=0;kh<3;kh++){
        int h2 = hh + kh - 1;
        if (h2 < 0 || h2 > 31) continue;
        #pragma unroll
        for (int kw=0;kw<3;kw++){
          int w2 = ww + kw - 1;
          if (w2 < 0 || w2 > 31) continue;
          float xv = xs[p][h2*32 + w2];
          #pragma unroll
          for (int qc=0;qc<4;qc++) acc[qc] = fmaf(wt[qc][p][kh*3+kw], xv, acc[qc]);
        }
      }
    }
    #pragma unroll
    for (int qc=0;qc<4;qc++)
      outp[((size_t)((b*CC + c)*4 + qc))*NPIX + k] = acc[qc];
  }
}

// ---------------------------------------------------------------------------
extern "C" void kernel_launch(void* const* d_in, const int* in_sizes, int n_in,
                              void* d_out, int out_size){
  const float* x      = (const float*)d_in[0];
  const float* w_qkv  = (const float*)d_in[1];
  const float* b_qkv  = (const float*)d_in[2];
  const float* w_proj = (const float*)d_in[3];
  const float* b_proj = (const float*)d_in[4];
  const float* w_pe   = (const float*)d_in[5];
  const float* b_pe   = (const float*)d_in[6];
  float* outp = (float*)d_out;

  (void)in_sizes; (void)n_in; (void)out_size;

  static cudaStream_t s2 = nullptr;
  static cudaEvent_t eFork = nullptr, eJoin = nullptr;
  if (s2 == nullptr){
    cudaStreamCreateWithFlags(&s2, cudaStreamNonBlocking);
    cudaEventCreateWithFlags(&eFork, cudaEventDisableTiming);
    cudaEventCreateWithFlags(&eJoin, cudaEventDisableTiming);
  }

  cudaFuncSetAttribute(gemm_mma<0>, cudaFuncAttributeMaxDynamicSharedMemorySize,
                       GEMM_SMEM);
  cudaFuncSetAttribute(gemm_mma<1>, cudaFuncAttributeMaxDynamicSharedMemorySize,
                       GEMM_SMEM);
  cudaFuncSetAttribute(attn_mma, cudaFuncAttributeMaxDynamicSharedMemorySize,
                       AT_SMEM);

  // ---- fork: dwconv runs on side stream, concurrent with the main chain ----
  cudaEventRecord(eFork, 0);
  cudaStreamWaitEvent(s2, eFork, 0);
  qdwconv_kernel<<< NB*CC, 256, 0, s2 >>>(x, w_pe, b_pe, outp);
  cudaEventRecord(eJoin, s2);

  // ---- main chain ----
  void *weffH, *wprojH;
  cudaGetSymbolAddress(&weffH, g_WeffH);
  cudaGetSymbolAddress(&wprojH, g_WprojH);
  prep_w_kernel<<< MQKV*128/256, 256 >>>(w_qkv, (char*)weffH, 1);
  prep_w_kernel<<< DIM*128/256, 256 >>>(w_proj, (char*)wprojH, 0);
  prep_xt_kernel<<< dim3(32,32,8), 256 >>>(x);

  // QKV GEMM: emits Q fp16 hi/lo, K fp16, V fp16 tiles directly
  gemm_mma<0><<< dim3(12,64), 256, GEMM_SMEM >>>(b_qkv, nullptr);

  // Attention: fp16x2 flash, 8 q-tiles x 64 (b,h)
  attn_mma<<< dim3(8,64), 256, AT_SMEM >>>();

  // ---- join: dwconv output must be in place before proj accumulates ----
  cudaStreamWaitEvent(0, eJoin, 0);

  // Proj: (1024 x 8192) fp16x2 -> accumulate into final output
  gemm_mma<1><<< dim3(4,64), 256, GEMM_SMEM >>>(b_proj, outp);
}

// round 12
// speedup vs baseline: 2.1610x; 1.5363x over previous
#include <cuda_runtime.h>
#include <cuda_bf16.h>
#include <cuda_fp16.h>
#include <cstdint>
#include <math.h>

#define NB 8
#define CC 256
#define NPIX 1024
#define HEADS 8
#define HD 128
#define MQKV 3072
#define DIM 1024

// Hamilton tables
__constant__ int   c_IDX[16] = {0,1,2,3, 1,0,3,2, 2,3,0,1, 3,2,1,0};
__constant__ float c_SGN[16] = {1.f,-1.f,-1.f,-1.f, 1.f,1.f,1.f,-1.f,
                                1.f,-1.f,1.f,1.f, 1.f,1.f,-1.f,1.f};

// Scratch (device globals). ALL tensor-core operands pre-tiled + pre-swizzled
// (fp16 hi only), fetched with single cp.async.bulk copies.
__device__ __half g_WeffH[(size_t)MQKV*DIM];
__device__ __half g_WprojH[(size_t)DIM*DIM];
__device__ __half g_XTH[(size_t)NB*NPIX*DIM];
__device__ __half g_OTH[(size_t)NB*NPIX*DIM];
__device__ __half g_QTH[(size_t)NB*HEADS*NPIX*HD];  // scale*log2e folded
__device__ __half g_KTH[(size_t)NB*HEADS*NPIX*HD];
__device__ __half g_VH[(size_t)NB*HEADS*HD*NPIX];

// ===========================================================================
// Helpers
// ===========================================================================
__device__ __forceinline__ uint32_t smem_u32(const void* p){
  uint32_t a;
  asm("{ .reg .u64 t; cvta.to.shared.u64 t, %1; cvt.u32.u64 %0, t; }"
      : "=r"(a) : "l"(p));
  return a;
}
__device__ __forceinline__ void ldm4(uint32_t r[4], uint32_t addr){
  asm volatile("ldmatrix.sync.aligned.m8n8.x4.shared.b16 {%0,%1,%2,%3}, [%4];"
    : "=r"(r[0]),"=r"(r[1]),"=r"(r[2]),"=r"(r[3]) : "r"(addr));
}
__device__ __forceinline__ void mma16816h(float c[4], const uint32_t a[4],
                                          const uint32_t b[2]){
  asm volatile(
    "mma.sync.aligned.m16n8k16.row.col.f32.f16.f16.f32 "
    "{%0,%1,%2,%3}, {%4,%5,%6,%7}, {%8,%9}, {%0,%1,%2,%3};"
    : "+f"(c[0]),"+f"(c[1]),"+f"(c[2]),"+f"(c[3])
    : "r"(a[0]),"r"(a[1]),"r"(a[2]),"r"(a[3]), "r"(b[0]),"r"(b[1]));
}
__device__ __forceinline__ uint32_t pkhf2(float a, float b){
  __half2 t = __floats2half2_rn(a, b);
  return *(uint32_t*)&t;
}
#define BULKCP(dst, src, bytes, mb) \
  asm volatile("cp.async.bulk.shared::cluster.global.mbarrier::complete_tx::bytes [%0], [%1], %2, [%3];" \
    :: "r"((uint32_t)(dst)), "l"(src), "r"((uint32_t)(bytes)), "r"((uint32_t)(mb)) : "memory")
#define MBARRIER_INIT(mb, c) \
  asm volatile("mbarrier.init.shared.b64 [%0], %1;" :: "r"((uint32_t)(mb)), "r"((uint32_t)(c)) : "memory")
#define MBARRIER_EXPECT_TX(mb, tx) \
  asm volatile("mbarrier.arrive.expect_tx.shared.b64 _, [%0], %1;" :: "r"((uint32_t)(mb)), "r"((uint32_t)(tx)) : "memory")
#define MBARRIER_WAIT_PARITY(mb, ph) do { \
    uint32_t _m = (uint32_t)(mb); uint32_t _p = (uint32_t)(ph); uint32_t _d; \
    asm volatile("{\n\t.reg .pred p;\n\t" \
        "mbarrier.try_wait.parity.acquire.cta.shared::cta.b64 p, [%1], %2;\n\t" \
        "selp.b32 %0, 1, 0, p;\n\t}" : "=r"(_d) : "r"(_m), "r"(_p) : "memory"); \
    if (!_d) { \
      asm volatile("{\n\t.reg .pred P1;\n\t" \
        "WL_%=:\n\t" \
        "mbarrier.try_wait.parity.acquire.cta.shared::cta.b64 P1, [%0], %1, 0x989680;\n\t" \
        "@P1 bra.uni WD_%=;\n\t" \
        "bra.uni WL_%=;\n\t" \
        "WD_%=:\n\t}" :: "r"(_m), "r"(_p) : "memory"); \
    } \
  } while(0)

// swizzled byte offsets inside tiles (row-major rows of 64/128/256 bytes)
__device__ __forceinline__ uint32_t swz64 (uint32_t r, uint32_t c16){ return r*64u  + ((c16 ^ ((r>>1)&3u))<<4); }
__device__ __forceinline__ uint32_t swz128(uint32_t r, uint32_t c16){ return r*128u + ((c16 ^ (r&7u))<<4); }
__device__ __forceinline__ uint32_t swz256(uint32_t r, uint32_t c16){ return r*256u + ((c16 ^ (r&7u))<<4); }

// ===========================================================================
// Prep: Hamilton-folded weights -> fp16, tiled+swizzled
// ===========================================================================
__global__ void prep_w_kernel(const float* __restrict__ w,
                              char* __restrict__ outH, int is_qkv){
  int idx = blockIdx.x*256 + threadIdx.x;
  int g = idx >> 7, c = idx & 127;
  int k0 = c*8;
  int qc, o;
  if (is_qkv){ qc = g / 768; o = g - qc*768; } else { qc = g >> 8; o = g & 255; }
  int p = k0 >> 8, cch = k0 & 255;
  float s = c_SGN[qc*4+p];
  const float* src = w + ((size_t)(c_IDX[qc*4+p]*(is_qkv?768:256) + o))*256 + cch;
  float4 v0 = *(const float4*)src;
  float4 v1 = *(const float4*)(src+4);
  size_t base = ((size_t)((g>>8)*32 + (c>>2)))*16384;
  uint32_t off = swz64(g & 255, c & 3);
  uint4 H;
  H.x = pkhf2(v0.x*s, v0.y*s); H.y = pkhf2(v0.z*s, v0.w*s);
  H.z = pkhf2(v1.x*s, v1.y*s); H.w = pkhf2(v1.z*s, v1.w*s);
  *(uint4*)(outH + base + off) = H;
}

// x (b, cch, p, n) fp32 -> XT tiles (b, ntile, kt) fp16
__global__ void prep_xt_kernel(const float* __restrict__ x){
  __shared__ float sm[32][33];
  int b = blockIdx.z, k0 = blockIdx.x*32, n0 = blockIdx.y*32;
  int t = threadIdx.x;
  {
    int kk = t >> 3, n4 = (t & 7) << 2;
    int k = k0 + kk; int p = k >> 8, cch = k & 255;
    float4 v = *(const float4*)&x[((size_t)((b*CC+cch)*4 + p))*NPIX + n0 + n4];
    sm[kk][n4] = v.x; sm[kk][n4+1] = v.y; sm[kk][n4+2] = v.z; sm[kk][n4+3] = v.w;
  }
  __syncthreads();
  {
    int nn = t >> 3, k4 = (t & 7) << 2;
    int n = n0 + nn;
    uint2 hp = make_uint2(pkhf2(sm[k4+0][nn], sm[k4+1][nn]),
                          pkhf2(sm[k4+2][nn], sm[k4+3][nn]));
    size_t tb = ((size_t)((b*8 + (n>>7))*32 + (k0>>5)))*8192;
    uint32_t off = swz64(n & 127, k4 >> 3) + ((k4 >> 2) & 1)*8;
    *(uint2*)((char*)g_XTH + tb + off) = hp;
  }
}

// ===========================================================================
// Pure fp16 GEMM: 256m x 128n per CTA, K=1024, BK=64 bulk-fed, 1 mma pass.
// MODE 0: A=Weff, B=XT. Fused epilogue -> Q (scaled), K, V fp16 tiles.
// MODE 1: A=Wproj, B=OT. Accumulates into final out (+bias).
// ===========================================================================
#define GSTG 49152u
#define GEMM_SMEM 136192u   // max(1024 + 2*GSTG, 1024 + 256*132*4 epilogue T)

template<int MODE>
__global__ __launch_bounds__(256, 1) void gemm_mma(const float* __restrict__ bias,
                                                   float* __restrict__ outp){
  extern __shared__ char smem[];
  const uint32_t sb = smem_u32(smem);
  const int tid = threadIdx.x;
  const int wid = tid >> 5, lane = tid & 31;
  const int mt = blockIdx.x;
  const int b  = blockIdx.y >> 3;
  const int nt = blockIdx.y & 7;
  const int m0 = mt*256, n0 = nt*128;
  const int wm = (wid >> 1) * 64;
  const int wn = (wid & 1) * 64;

  const char* Ahb = (const char*)(MODE==0 ? (void*)g_WeffH : (void*)g_WprojH) + (size_t)mt*32*16384;
  const char* Bhb = (const char*)(MODE==0 ? (void*)g_XTH : (void*)g_OTH) + (size_t)((b*8+nt)*32)*8192;

  if (tid == 0){ MBARRIER_INIT(sb+8, 1); MBARRIER_INIT(sb+16, 1); }
  __syncthreads();

  float acc[4][8][4];
  #pragma unroll
  for (int i=0;i<4;i++)
    #pragma unroll
    for (int j=0;j<8;j++)
      #pragma unroll
      for (int r=0;r<4;r++) acc[i][j][r] = 0.f;

  auto issue = [&](int kt2){
    if (tid == 0){
      int buf = kt2 & 1;
      uint32_t mb = sb + 8 + buf*8;
      MBARRIER_EXPECT_TX(mb, GSTG);
      uint32_t d = sb + 1024 + buf*GSTG;
      BULKCP(d,         Ahb + (size_t)kt2*32768, 32768, mb);
      BULKCP(d+32768,   Bhb + (size_t)kt2*16384, 16384, mb);
    }
  };

  issue(0);
  for (int kt2 = 0; kt2 < 16; kt2++){
    if (kt2 + 1 < 16) issue(kt2+1);
    MBARRIER_WAIT_PARITY(sb + 8 + (kt2&1)*8, (kt2>>1)&1);
    const uint32_t st = sb + 1024 + (kt2&1)*GSTG;

    #pragma unroll
    for (int s = 0; s < 2; s++){
      const uint32_t Ah = st + s*16384;
      const uint32_t Bh = st + 32768 + s*8192;
      #pragma unroll
      for (int ks = 0; ks < 2; ks++){
        uint32_t ah[4][4], bh[8][2];
        #pragma unroll
        for (int mi = 0; mi < 4; mi++){
          uint32_t row = wm + mi*16 + (lane & 15);
          uint32_t c16 = ks*2 + (lane >> 4);
          ldm4(ah[mi], Ah + swz64(row, c16));
        }
        #pragma unroll
        for (int np = 0; np < 4; np++){
          uint32_t row = wn + np*16 + (lane >> 4)*8 + (lane & 7);
          uint32_t c16 = ks*2 + ((lane >> 3) & 1);
          uint32_t r[4];
          ldm4(r, Bh + swz64(row, c16));
          bh[np*2][0]=r[0]; bh[np*2][1]=r[1]; bh[np*2+1][0]=r[2]; bh[np*2+1][1]=r[3];
        }
        #pragma unroll
        for (int mi=0;mi<4;mi++)
          #pragma unroll
          for (int ni=0;ni<8;ni++) mma16816h(acc[mi][ni], ah[mi], bh[ni]);
      }
    }
    __syncthreads();
  }

  if (MODE == 1){
    // final output: out[(b, cch, qc, n)] += acc + bias  (dwconv pre-wrote)
    #pragma unroll
    for (int mi=0;mi<4;mi++)
      #pragma unroll
      for (int half=0; half<2; half++){
        int gm = m0 + wm + mi*16 + (lane >> 2) + half*8;
        float bi = bias[gm];
        int qc = gm >> 8; int cch = gm & 255;
        float* dst = outp + ((size_t)((b*CC + cch)*4 + qc))*NPIX;
        #pragma unroll
        for (int ni=0;ni<8;ni++){
          int nn = n0 + wn + ni*8 + (lane & 3)*2;
          float2 old = *(float2*)&dst[nn];
          float2 v = make_float2(old.x + acc[mi][ni][half*2+0] + bi,
                                 old.y + acc[mi][ni][half*2+1] + bi);
          *(float2*)&dst[nn] = v;
        }
      }
    return;
  }

  // ---- MODE 0 epilogue: region = Q(0) / K(1) / V(2) ----
  const int region = mt % 3;
  const int qc = mt / 3;
  if (region == 2){
    // V: fp16 stores into (d, n) tiles
    #pragma unroll
    for (int mi=0;mi<4;mi++)
      #pragma unroll
      for (int half=0; half<2; half++){
        int gm = m0 + wm + mi*16 + (lane >> 2) + half*8;
        float bi = bias[gm];
        int o = gm - qc*768; int cch = o & 255;
        int ch = (qc << 8) | cch; int hh = ch >> 7; int dd = ch & 127;
        size_t bhbase = ((size_t)(b*HEADS + hh))*16*16384;
        #pragma unroll
        for (int ni=0;ni<8;ni++){
          int nn = n0 + wn + ni*8 + (lane & 3)*2;
          float v0 = acc[mi][ni][half*2+0] + bi;
          float v1 = acc[mi][ni][half*2+1] + bi;
          size_t tb = bhbase + (size_t)(nn>>6)*16384;
          uint32_t off = swz128(dd, (nn&63)>>3) + (nn&7)*2;
          *(uint32_t*)((char*)g_VH + tb + off) = pkhf2(v0, v1);
        }
      }
  } else {
    // Q/K: stage fp32 into smem (scale folded), transpose, emit (n,d) tiles
    float* T = (float*)(smem + 1024);   // 256 x 132 fp32 = 135168 B
    const float scl = (region == 0) ? 0.12751875542484462f  // qscale*log2e
                                    : 1.f;
    #pragma unroll
    for (int mi=0;mi<4;mi++)
      #pragma unroll
      for (int half=0; half<2; half++){
        int gm = m0 + wm + mi*16 + (lane >> 2) + half*8;
        int row = gm - m0;
        float bi = bias[gm];
        #pragma unroll
        for (int ni=0;ni<8;ni++){
          int nn = wn + ni*8 + (lane & 3)*2;
          T[row*132 + nn]     = (acc[mi][ni][half*2+0] + bi)*scl;
          T[row*132 + nn + 1] = (acc[mi][ni][half*2+1] + bi)*scl;
        }
      }
    __syncthreads();

    char* dh = (region == 0) ? (char*)g_QTH : (char*)g_KTH;
    const int nl = tid & 127;
    const int hp = tid >> 7;            // head parity within tile
    const int n = n0 + nl;
    const int head = qc*2 + hp;
    const size_t tb = ((size_t)((b*HEADS + head)*16 + (n>>6)))*16384;
    const uint32_t r6 = n & 63;
    #pragma unroll
    for (int c16 = 0; c16 < 16; c16++){
      float a[8];
      #pragma unroll
      for (int i=0;i<8;i++) a[i] = T[(hp*128 + c16*8 + i)*132 + nl];
      uint4 H;
      H.x = pkhf2(a[0],a[1]); H.y = pkhf2(a[2],a[3]);
      H.z = pkhf2(a[4],a[5]); H.w = pkhf2(a[6],a[7]);
      *(uint4*)(dh + tb + swz256(r6, c16)) = H;
    }
  }
}

// ===========================================================================
// Flash attention, pure fp16. S = Qh*Kh; PV = Ph*Vh.
// CTA = (b,h) x 128 queries, 256 thr, 8 warps x 16 q-rows.
// ===========================================================================
#define ASTG 32768u
#define AT_SMEM (1024u + 2u*ASTG)

__global__ __launch_bounds__(256, 1) void attn_mma(){
  extern __shared__ char smem[];
  const uint32_t sb = smem_u32(smem);
  const int tid = threadIdx.x;
  const int wid = tid >> 5, lane = tid & 31;
  const int bh = blockIdx.y;
  const int qi = blockIdx.x;           // q block of 128
  const int q0 = qi * 128;
  const int b = bh >> 3, h = bh & 7;

  if (tid == 0){
    MBARRIER_INIT(sb+8, 1); MBARRIER_INIT(sb+16, 1); MBARRIER_INIT(sb+24, 1);
  }
  __syncthreads();

  // ---- Q load: 2 tiles = 32KB into the stage region
  if (tid == 0){
    MBARRIER_EXPECT_TX(sb+24, 32768);
    const char* qh_g = (const char*)g_QTH + ((size_t)bh*16 + qi*2)*16384;
    BULKCP(sb+1024, qh_g, 32768, sb+24);
  }
  MBARRIER_WAIT_PARITY(sb+24, 0);

  uint32_t qfh[8][4];
  {
    uint32_t row = wid*16 + (lane & 15);
    uint32_t base = sb + 1024 + (row >> 6)*16384;
    uint32_t r6 = row & 63;
    #pragma unroll
    for (int kf = 0; kf < 8; kf++){
      uint32_t c16 = kf*2 + (lane >> 4);
      ldm4(qfh[kf], base + swz256(r6, c16));
    }
  }
  __syncthreads();   // Q consumed; stage region reusable

  const char* kh_g = (const char*)g_KTH + (size_t)bh*16*16384;
  const char* vh_g = (const char*)g_VH  + (size_t)bh*16*16384;

  auto issueKV = [&](int kb){
    if (tid == 0){
      int buf = kb & 1;
      uint32_t mb = sb + 8 + buf*8;
      MBARRIER_EXPECT_TX(mb, ASTG);
      uint32_t d = sb + 1024 + buf*ASTG;
      BULKCP(d,         kh_g + (size_t)kb*16384, 16384, mb);
      BULKCP(d+16384,   vh_g + (size_t)kb*16384, 16384, mb);
    }
  };

  float accO[16][4];
  #pragma unroll
  for (int i=0;i<16;i++)
    #pragma unroll
    for (int r=0;r<4;r++) accO[i][r] = 0.f;
  float m0r = -1e30f, m1r = -1e30f, l0 = 0.f, l1 = 0.f;

  issueKV(0);
  for (int kb = 0; kb < 16; kb++){
    if (kb + 1 < 16) issueKV(kb+1);
    MBARRIER_WAIT_PARITY(sb + 8 + (kb&1)*8, (kb>>1)&1);
    const uint32_t st = sb + 1024 + (kb&1)*ASTG;

    // ---- S = Qh Kh^T  (16q x 64k per warp)
    float S[8][4];
    #pragma unroll
    for (int i=0;i<8;i++)
      #pragma unroll
      for (int r=0;r<4;r++) S[i][r] = 0.f;
    #pragma unroll
    for (int kf = 0; kf < 8; kf++){
      #pragma unroll
      for (int np = 0; np < 4; np++){
        uint32_t row = np*16 + (lane >> 4)*8 + (lane & 7);
        uint32_t c16 = kf*2 + ((lane >> 3) & 1);
        uint32_t r[4];
        ldm4(r, st + swz256(row, c16));
        uint32_t b0[2] = {r[0], r[1]}, b1[2] = {r[2], r[3]};
        mma16816h(S[np*2],   qfh[kf], b0);
        mma16816h(S[np*2+1], qfh[kf], b1);
      }
    }

    // ---- online softmax (log2 domain; log2e folded into Q)
    float mx0 = -1e30f, mx1 = -1e30f;
    #pragma unroll
    for (int i=0;i<8;i++){
      mx0 = fmaxf(mx0, fmaxf(S[i][0], S[i][1]));
      mx1 = fmaxf(mx1, fmaxf(S[i][2], S[i][3]));
    }
    mx0 = fmaxf(mx0, __shfl_xor_sync(0xffffffffu, mx0, 1));
    mx0 = fmaxf(mx0, __shfl_xor_sync(0xffffffffu, mx0, 2));
    mx1 = fmaxf(mx1, __shfl_xor_sync(0xffffffffu, mx1, 1));
    mx1 = fmaxf(mx1, __shfl_xor_sync(0xffffffffu, mx1, 2));
    float mn0 = fmaxf(m0r, mx0), mn1 = fmaxf(m1r, mx1);
    float al0 = exp2f(m0r - mn0), al1 = exp2f(m1r - mn1);
    m0r = mn0; m1r = mn1;

    float rs0 = 0.f, rs1 = 0.f;
    uint32_t ph[4][4];
    #pragma unroll
    for (int nf = 0; nf < 8; nf++){
      float p0 = exp2f(S[nf][0] - mn0);
      float p1 = exp2f(S[nf][1] - mn0);
      float p2 = exp2f(S[nf][2] - mn1);
      float p3 = exp2f(S[nf][3] - mn1);
      rs0 += p0 + p1; rs1 += p2 + p3;
      int kf = nf >> 1, pc = (nf & 1)*2;
      ph[kf][pc+0] = pkhf2(p0, p1);
      ph[kf][pc+1] = pkhf2(p2, p3);
    }
    rs0 += __shfl_xor_sync(0xffffffffu, rs0, 1);
    rs0 += __shfl_xor_sync(0xffffffffu, rs0, 2);
    rs1 += __shfl_xor_sync(0xffffffffu, rs1, 1);
    rs1 += __shfl_xor_sync(0xffffffffu, rs1, 2);
    l0 = l0*al0 + rs0; l1 = l1*al1 + rs1;

    #pragma unroll
    for (int i=0;i<16;i++){
      accO[i][0] *= al0; accO[i][1] *= al0;
      accO[i][2] *= al1; accO[i][3] *= al1;
    }

    // ---- accO += Ph Vh  (16q x 128d per warp)
    const uint32_t vb = st + 16384;
    #pragma unroll
    for (int kf = 0; kf < 4; kf++){
      #pragma unroll
      for (int np = 0; np < 8; np++){
        uint32_t row = np*16 + (lane >> 4)*8 + (lane & 7);
        uint32_t c16 = kf*2 + ((lane >> 3) & 1);
        uint32_t r[4];
        ldm4(r, vb + swz128(row, c16));
        uint32_t b0[2] = {r[0], r[1]}, b1[2] = {r[2], r[3]};
        mma16816h(accO[np*2],   ph[kf], b0);
        mma16816h(accO[np*2+1], ph[kf], b1);
      }
    }
    __syncthreads();
  }

  // ---- epilogue: O/l -> fp16 into tiled OT
  float inv0 = 1.f / l0, inv1 = 1.f / l1;
  int na = q0 + wid*16 + (lane >> 2);
  int nb2 = na + 8;
  #pragma unroll
  for (int nf = 0; nf < 16; nf++){
    int ch = h*HD + nf*8 + (lane & 3)*2;
    float v0 = accO[nf][0]*inv0, v1 = accO[nf][1]*inv0;
    float v2 = accO[nf][2]*inv1, v3 = accO[nf][3]*inv1;
    size_t tba = ((size_t)((b*8 + (na>>7))*32 + (ch>>5)))*8192;
    size_t tbb = ((size_t)((b*8 + (nb2>>7))*32 + (ch>>5)))*8192;
    uint32_t ofa = swz64(na & 127, (ch>>3)&3) + (ch&7)*2;
    uint32_t ofb = swz64(nb2 & 127, (ch>>3)&3) + (ch&7)*2;
    *(uint32_t*)((char*)g_OTH + tba + ofa) = pkhf2(v0, v1);
    *(uint32_t*)((char*)g_OTH + tbb + ofb) = pkhf2(v2, v3);
  }
}

// ---------------------------------------------------------------------------
// Quaternion depthwise 3x3. WRITES (=) conv + pe-bias to output; proj GEMM
// accumulates on top. Runs on a side stream concurrent with the main chain.
// ---------------------------------------------------------------------------
__global__ __launch_bounds__(256) void qdwconv_kernel(const float* __restrict__ x,
                                                      const float* __restrict__ w_pe,
                                                      const float* __restrict__ b_pe,
                                                      float* __restrict__ outp){
  __shared__ float xs[4][1024];
  __shared__ float wt[4][4][9];
  const int bid = blockIdx.x;
  const int c = bid & 255, b = bid >> 8;
  const int tid = threadIdx.x;

  #pragma unroll
  for (int p=0;p<4;p++){
    const float* xp = x + ((size_t)((b*CC + c)*4 + p))*NPIX;
    for (int k=tid; k<1024; k+=256) xs[p][k] = xp[k];
  }
  if (tid < 144){
    int qc = tid/36, p = (tid/9)&3, t = tid%9;
    wt[qc][p][t] = c_SGN[qc*4+p] * w_pe[(c_IDX[qc*4+p]*CC + c)*9 + t];
  }
  __syncthreads();

  float bia[4];
  #pragma unroll
  for (int qc=0;qc<4;qc++) bia[qc] = b_pe[qc*CC + c];

  for (int k=tid; k<1024; k+=256){
    int hh = k >> 5, ww = k & 31;
    float acc[4] = {bia[0],bia[1],bia[2],bia[3]};
    #pragma unroll
    for (int p=0;p<4;p++){
      #pragma unroll
      for (int kh=0;kh<3;kh++){
        int h2 = hh + kh - 1;
        if (h2 < 0 || h2 > 31) continue;
        #pragma unroll
        for (int kw=0;kw<3;kw++){
          int w2 = ww + kw - 1;
          if (w2 < 0 || w2 > 31) continue;
          float xv = xs[p][h2*32 + w2];
          #pragma unroll
          for (int qc=0;qc<4;qc++) acc[qc] = fmaf(wt[qc][p][kh*3+kw], xv, acc[qc]);
        }
      }
    }
    #pragma unroll
    for (int qc=0;qc<4;qc++)
      outp[((size_t)((b*CC + c)*4 + qc))*NPIX + k] = acc[qc];
  }
}

// ---------------------------------------------------------------------------
extern "C" void kernel_launch(void* const* d_in, const int* in_sizes, int n_in,
                              void* d_out, int out_size){
  const float* x      = (const float*)d_in[0];
  const float* w_qkv  = (const float*)d_in[1];
  const float* b_qkv  = (const float*)d_in[2];
  const float* w_proj = (const float*)d_in[3];
  const float* b_proj = (const float*)d_in[4];
  const float* w_pe   = (const float*)d_in[5];
  const float* b_pe   = (const float*)d_in[6];
  float* outp = (float*)d_out;

  (void)in_sizes; (void)n_in; (void)out_size;

  static cudaStream_t s2 = nullptr;
  static cudaEvent_t eFork = nullptr, eJoin = nullptr;
  if (s2 == nullptr){
    cudaStreamCreateWithFlags(&s2, cudaStreamNonBlocking);
    cudaEventCreateWithFlags(&eFork, cudaEventDisableTiming);
    cudaEventCreateWithFlags(&eJoin, cudaEventDisableTiming);
  }

  cudaFuncSetAttribute(gemm_mma<0>, cudaFuncAttributeMaxDynamicSharedMemorySize,
                       GEMM_SMEM);
  cudaFuncSetAttribute(gemm_mma<1>, cudaFuncAttributeMaxDynamicSharedMemorySize,
                       GEMM_SMEM);
  cudaFuncSetAttribute(attn_mma, cudaFuncAttributeMaxDynamicSharedMemorySize,
                       AT_SMEM);

  // ---- fork: dwconv runs on side stream, concurrent with the main chain ----
  cudaEventRecord(eFork, 0);
  cudaStreamWaitEvent(s2, eFork, 0);
  qdwconv_kernel<<< NB*CC, 256, 0, s2 >>>(x, w_pe, b_pe, outp);
  cudaEventRecord(eJoin, s2);

  // ---- main chain ----
  void *weffH, *wprojH;
  cudaGetSymbolAddress(&weffH, g_WeffH);
  cudaGetSymbolAddress(&wprojH, g_WprojH);
  prep_w_kernel<<< MQKV*128/256, 256 >>>(w_qkv, (char*)weffH, 1);
  prep_w_kernel<<< DIM*128/256, 256 >>>(w_proj, (char*)wprojH, 0);
  prep_xt_kernel<<< dim3(32,32,8), 256 >>>(x);

  // QKV GEMM: emits Q (scaled), K, V fp16 tiles directly
  gemm_mma<0><<< dim3(12,64), 256, GEMM_SMEM >>>(b_qkv, nullptr);

  // Attention: pure fp16 flash, 8 q-tiles x 64 (b,h)
  attn_mma<<< dim3(8,64), 256, AT_SMEM >>>();

  // ---- join: dwconv output must be in place before proj accumulates ----
  cudaStreamWaitEvent(0, eJoin, 0);

  // Proj: (1024 x 8192) fp16 -> accumulate into final output
  gemm_mma<1><<< dim3(4,64), 256, GEMM_SMEM >>>(b_proj, outp);
}